// round 12
// baseline (speedup 1.0000x reference)
#include <cuda_runtime.h>
#include <math.h>
#include <stdint.h>

// Problem constants
#define BB 4
#define TT 64
#define CC 512
#define HW 196          // 14*14 spatial positions
#define BN (BB*HW)      // 784
#define NROWS (BN*TT)   // 50176
#define NH 8
#define DH 64
#define KTOP 19         // int(0.3*64)
#define ALPHA 0.2f
// DistanceAdj band: reference computes adj0=exp(-(0.6d^2+0.2)) with XLA-CPU's
// Eigen pexp, which FLUSHES results below the smallest normal f32 (cannot emit
// denormals). exp(-arg) >= 1.18e-38 iff arg <= 87.34 iff |d| <= 12.
// (d=13 -> 7.5e-45 would be denormal -> flushed to 0 by Eigen -> masked.)
#define DBAND 12

// -------- device global scratch --------
__device__ float g_xr[(size_t)NROWS * CC];    // [BN,T,C]
__device__ float g_y [(size_t)NROWS * CC];    // pre-LN result
__device__ float2 g_stats[NROWS];             // (mu, rstd)

// -------- kernel 1: transpose x[B,T,C,HW] -> xr[BN,T,C] --------
__global__ void transpose_in_kernel(const float* __restrict__ x) {
    __shared__ float tile[32][33];
    int bt = blockIdx.z;                  // b*64+t
    int n0 = blockIdx.x * 32;
    int c0 = blockIdx.y * 32;
    int tx = threadIdx.x, ty = threadIdx.y;
    int b = bt >> 6, t = bt & 63;
#pragma unroll
    for (int i = 0; i < 4; i++) {
        int cl = ty + i * 8;
        int n = n0 + tx;
        if (n < HW)
            tile[cl][tx] = x[((size_t)bt * CC + (c0 + cl)) * HW + n];
    }
    __syncthreads();
#pragma unroll
    for (int i = 0; i < 4; i++) {
        int nl = ty + i * 8;
        int n = n0 + nl;
        if (n < HW)
            g_xr[(((size_t)(b * HW + n)) * TT + t) * CC + c0 + tx] = tile[tx][nl];
    }
}

// -------- kernel 2: fully fused per-bn GAT module --------
__global__ __launch_bounds__(256) void fused_attn_kernel(
    const float* __restrict__ Wg, const float* __restrict__ a1g,
    const float* __restrict__ a2g, float* __restrict__ tmp_out) {
    __shared__ float As[16][64];     // xr k-tile: [k][t]
    __shared__ float Bs[16][68];     // Wg k-tile: [k][d] (pad)
    __shared__ float hh[64][68];     // h tile [t][d]
    __shared__ float att[64][68];    // softmax matrix [t][s]; reused for col partials
    __shared__ float f1[64], f2[64]; // f1 reused as inv-norm per column
    __shared__ float smag[64];
    __shared__ float sa1[64], sa2[64];
    __shared__ int   ssel[64];
    __shared__ float magp[64][5];

    const int bn  = blockIdx.x;
    const int tid = threadIdx.x;
    const float* __restrict__ slab = g_xr + (size_t)bn * TT * CC;  // [64][512]

    // ---- mags: 4 threads per t, each sums 128 channels ----
    {
        int t = tid >> 2, q = tid & 3;
        float s = 0.f;
        const float* p = slab + (size_t)t * CC + q * 128;
#pragma unroll 8
        for (int c = 0; c < 128; c++) { float v = p[c]; s = fmaf(v, v, s); }
        magp[t][q] = s;
    }
    __syncthreads();
    if (tid < 64)
        smag[tid] = sqrtf(magp[tid][0] + magp[tid][1] + magp[tid][2] + magp[tid][3]);
    __syncthreads();
    if (tid < 64) {
        // top-k selection (rank with index tiebreak, matches lax.top_k)
        float m = smag[tid];
        int rank = 0;
#pragma unroll 8
        for (int s = 0; s < 64; s++) {
            float ms = smag[s];
            rank += (ms > m) || (ms == m && s < tid);
        }
        ssel[tid] = (rank < KTOP) ? 1 : 0;
    }

    const int tm = tid >> 4, tn = tid & 15;      // 16x16 thread grid, 4x4 micro-tiles
    const int ar = tid >> 2, ak = (tid & 3) * 4; // A-load roles
    const int bk = tid >> 4, bj = (tid & 15) * 4;// B-load roles
    const int warp = tid >> 5, lane = tid & 31;
    const int t4 = tm * 4, d4 = tn * 4;

    for (int head = 0; head < NH; head++) {
        const float* __restrict__ Wh = Wg + (size_t)head * CC * DH;  // [512][64]

        // ---- h-GEMM: hh[t][d] = sum_c slab[t][c] * Wh[c][d] ----
        float acc[4][4] = {};
        for (int k0 = 0; k0 < 512; k0 += 16) {
            float4 av = *reinterpret_cast<const float4*>(&slab[(size_t)ar * CC + k0 + ak]);
            As[ak + 0][ar] = av.x; As[ak + 1][ar] = av.y;
            As[ak + 2][ar] = av.z; As[ak + 3][ar] = av.w;
            float4 bv = *reinterpret_cast<const float4*>(&Wh[(size_t)(k0 + bk) * DH + bj]);
            *reinterpret_cast<float4*>(&Bs[bk][bj]) = bv;
            __syncthreads();
#pragma unroll
            for (int kk = 0; kk < 16; kk++) {
                float a_[4], b_[4];
#pragma unroll
                for (int i = 0; i < 4; i++) a_[i] = As[kk][t4 + i];
#pragma unroll
                for (int j = 0; j < 4; j++) b_[j] = Bs[kk][d4 + j];
#pragma unroll
                for (int i = 0; i < 4; i++)
#pragma unroll
                    for (int j = 0; j < 4; j++)
                        acc[i][j] = fmaf(a_[i], b_[j], acc[i][j]);
            }
            __syncthreads();
        }
#pragma unroll
        for (int i = 0; i < 4; i++)
#pragma unroll
            for (int j = 0; j < 4; j++)
                hh[t4 + i][d4 + j] = acc[i][j];
        if (tid < 64)       sa1[tid]      = a1g[head * DH + tid];
        else if (tid < 128) sa2[tid - 64] = a2g[head * DH + (tid - 64)];
        __syncthreads();

        // ---- f1/f2 per t ----
        if (tid < 64) {
            float s1 = 0.f, s2 = 0.f;
#pragma unroll 16
            for (int d = 0; d < 64; d++) {
                float hv = hh[tid][d];
                s1 = fmaf(hv, sa1[d], s1);
                s2 = fmaf(hv, sa2[d], s2);
            }
            f1[tid] = s1; f2[tid] = s2;
        }
        __syncthreads();

        // ---- masked softmax: one warp per row, lanes cover s and s+32 ----
        // mask = (topk-union) AND |t-s| <= DBAND  (f32 flush band of adj0,
        // hardcoded as integer test so no exp implementation can change it)
        for (int t = warp; t < 64; t += 8) {
            int selt = ssel[t];
            float ft = f1[t];
            int s0 = lane, s1i = lane + 32;
            float e0 = ft + f2[s0];
            float e1 = ft + f2[s1i];
            e0 = fmaxf(e0, ALPHA * e0);          // leaky relu
            e1 = fmaxf(e1, ALPHA * e1);
            bool band0 = abs(t - s0)  <= DBAND;
            bool band1 = abs(t - s1i) <= DBAND;
            float l0 = ((selt | ssel[s0])  && band0) ? e0 : -9e15f;
            float l1 = ((selt | ssel[s1i]) && band1) ? e1 : -9e15f;
            float mx = fmaxf(l0, l1);
#pragma unroll
            for (int o = 16; o; o >>= 1) mx = fmaxf(mx, __shfl_xor_sync(~0u, mx, o));
            float p0 = __expf(l0 - mx), p1 = __expf(l1 - mx);
            float sumv = p0 + p1;
#pragma unroll
            for (int o = 16; o; o >>= 1) sumv += __shfl_xor_sync(~0u, sumv, o);
            float inv = 1.f / sumv;
            att[t][s0]  = p0 * inv;
            att[t][s1i] = p1 * inv;
        }
        __syncthreads();

        // ---- out = att @ h (4t x 4d per thread), then ELU + signed sqrt ----
        float acc2[4][4] = {};
        for (int s = 0; s < 64; s++) {
            float4 hv = *reinterpret_cast<const float4*>(&hh[s][d4]);
            float hb[4] = {hv.x, hv.y, hv.z, hv.w};
#pragma unroll
            for (int i = 0; i < 4; i++) {
                float a = att[t4 + i][s];
#pragma unroll
                for (int j = 0; j < 4; j++) acc2[i][j] = fmaf(a, hb[j], acc2[i][j]);
            }
        }
        float sv[4][4];       // signed sqrt of ELU output
        float part[4] = {0.f, 0.f, 0.f, 0.f};  // per-column |elu| partials (= sv^2)
#pragma unroll
        for (int i = 0; i < 4; i++)
#pragma unroll
            for (int j = 0; j < 4; j++) {
                float v = acc2[i][j];
                float e = v > 0.f ? v : expm1f(v);
                float ae = fabsf(e);
                sv[i][j] = copysignf(sqrtf(ae), e);
                part[j] += ae;
            }
        __syncthreads();      // att reads done; reuse att[][] as column partials
#pragma unroll
        for (int j = 0; j < 4; j++) att[tm][d4 + j] = part[j];
        __syncthreads();
        if (tid < 64) {       // reuse f1 as inverse column norm
            float tot = 0.f;
#pragma unroll
            for (int g = 0; g < 16; g++) tot += att[g][tid];
            f1[tid] = 1.f / fmaxf(sqrtf(tot), 1e-12f);
        }
        __syncthreads();

        // ---- scale + write tmp to d_out [bn][t][head*64+d] ----
#pragma unroll
        for (int i = 0; i < 4; i++) {
            float4 o4 = make_float4(sv[i][0] * f1[d4 + 0], sv[i][1] * f1[d4 + 1],
                                    sv[i][2] * f1[d4 + 2], sv[i][3] * f1[d4 + 3]);
            *reinterpret_cast<float4*>(
                &tmp_out[(size_t)bn * TT * CC + (size_t)(t4 + i) * CC + head * DH + d4]) = o4;
        }
        __syncthreads();
    }
}

// -------- kernel 3: g_y = tmp @ W2 + b2 + g_xr --------
__global__ __launch_bounds__(256) void gemm_out_kernel(
    const float* __restrict__ A, const float* __restrict__ Bsrc,
    const float* __restrict__ bias) {
    __shared__ float As[16][64];
    __shared__ float Bs[16][64];
    const int m0 = blockIdx.x * 64;
    const int n0 = blockIdx.y * 64;
    const int tid = threadIdx.x;
    const int tm = tid >> 4, tn = tid & 15;
    const int ar = tid >> 2, ak = (tid & 3) * 4;
    const int bk = tid >> 4, bj = (tid & 15) * 4;
    float acc[4][4] = {};
    for (int k0 = 0; k0 < 512; k0 += 16) {
        float4 av = *reinterpret_cast<const float4*>(&A[(size_t)(m0 + ar) * CC + k0 + ak]);
        As[ak + 0][ar] = av.x; As[ak + 1][ar] = av.y;
        As[ak + 2][ar] = av.z; As[ak + 3][ar] = av.w;
        float4 bv = *reinterpret_cast<const float4*>(&Bsrc[(size_t)(k0 + bk) * CC + n0 + bj]);
        *reinterpret_cast<float4*>(&Bs[bk][bj]) = bv;
        __syncthreads();
#pragma unroll
        for (int kk = 0; kk < 16; kk++) {
            float4 ra = *reinterpret_cast<const float4*>(&As[kk][tm * 4]);
            float4 rb = *reinterpret_cast<const float4*>(&Bs[kk][tn * 4]);
            float a_[4] = {ra.x, ra.y, ra.z, ra.w};
            float b_[4] = {rb.x, rb.y, rb.z, rb.w};
#pragma unroll
            for (int i = 0; i < 4; i++)
#pragma unroll
                for (int j = 0; j < 4; j++)
                    acc[i][j] = fmaf(a_[i], b_[j], acc[i][j]);
        }
        __syncthreads();
    }
#pragma unroll
    for (int i = 0; i < 4; i++) {
        int m = m0 + tm * 4 + i;
#pragma unroll
        for (int j = 0; j < 4; j++) {
            int n = n0 + tn * 4 + j;
            g_y[(size_t)m * CC + n] = acc[i][j] + bias[n] + g_xr[(size_t)m * CC + n];
        }
    }
}

// -------- kernel 4: LayerNorm stats per row --------
__global__ void ln_stats_kernel() {
    int row = blockIdx.x;
    const float* p = g_y + (size_t)row * CC;
    float s = 0.f, sq = 0.f;
    for (int c = threadIdx.x; c < CC; c += 128) {
        float v = p[c];
        s += v; sq = fmaf(v, v, sq);
    }
#pragma unroll
    for (int o = 16; o; o >>= 1) {
        s  += __shfl_xor_sync(~0u, s, o);
        sq += __shfl_xor_sync(~0u, sq, o);
    }
    __shared__ float rs[4], rq[4];
    if ((threadIdx.x & 31) == 0) { rs[threadIdx.x >> 5] = s; rq[threadIdx.x >> 5] = sq; }
    __syncthreads();
    if (threadIdx.x == 0) {
        float tot = rs[0] + rs[1] + rs[2] + rs[3];
        float totq = rq[0] + rq[1] + rq[2] + rq[3];
        float mu = tot * (1.f / CC);
        float var = totq * (1.f / CC) - mu * mu;
        g_stats[row] = make_float2(mu, rsqrtf(var + 1e-5f));
    }
}

// -------- kernel 5: apply LN + transpose back to [B,T,C,HW] --------
__global__ void transpose_out_kernel(const float* __restrict__ ln_g,
                                     const float* __restrict__ ln_b,
                                     float* __restrict__ out) {
    __shared__ float tile[32][33];
    int bt = blockIdx.z;
    int n0 = blockIdx.x * 32;
    int c0 = blockIdx.y * 32;
    int tx = threadIdx.x, ty = threadIdx.y;
    int b = bt >> 6, t = bt & 63;
    float lg = ln_g[c0 + tx], lb = ln_b[c0 + tx];
#pragma unroll
    for (int i = 0; i < 4; i++) {
        int nl = ty + i * 8;
        int n = n0 + nl;
        if (n < HW) {
            int bn = b * HW + n;
            float2 st = g_stats[bn * TT + t];
            float v = g_y[(((size_t)bn) * TT + t) * CC + c0 + tx];
            tile[nl][tx] = (v - st.x) * st.y * lg + lb;
        }
    }
    __syncthreads();
#pragma unroll
    for (int i = 0; i < 4; i++) {
        int cl = ty + i * 8;
        int n = n0 + tx;
        if (n < HW)
            out[((size_t)bt * CC + (c0 + cl)) * HW + n] = tile[tx][cl];
    }
}

extern "C" void kernel_launch(void* const* d_in, const int* in_sizes, int n_in,
                              void* d_out, int out_size) {
    const float* x    = (const float*)d_in[0];
    const float* Wg   = (const float*)d_in[1];
    const float* a1   = (const float*)d_in[2];
    const float* a2   = (const float*)d_in[3];
    const float* W2   = (const float*)d_in[4];
    const float* b2   = (const float*)d_in[5];
    const float* ln_g = (const float*)d_in[6];
    const float* ln_b = (const float*)d_in[7];
    float* out = (float*)d_out;

    // d_out doubles as the tmp buffer between fused_attn and gemm_out
    // (stream-ordered, fully overwritten by transpose_out at the end)
    transpose_in_kernel<<<dim3(7, 16, BB * TT), dim3(32, 8)>>>(x);
    fused_attn_kernel<<<BN, 256>>>(Wg, a1, a2, out);
    gemm_out_kernel<<<dim3(NROWS / 64, 8), 256>>>(out, W2, b2);
    ln_stats_kernel<<<NROWS, 128>>>();
    transpose_out_kernel<<<dim3(7, 16, BB * TT), dim3(32, 8)>>>(ln_g, ln_b, out);
}

// round 13
// speedup vs baseline: 2.2453x; 2.2453x over previous
#include <cuda_runtime.h>
#include <math.h>
#include <stdint.h>

// Problem constants
#define BB 4
#define TT 64
#define CC 512
#define HW 196          // 14*14 spatial positions
#define BN (BB*HW)      // 784
#define NROWS (BN*TT)   // 50176
#define NH 8
#define DH 64
#define KTOP 19         // int(0.3*64)
#define ALPHA 0.2f
// DistanceAdj band: reference's Eigen pexp flushes subnormal outputs ->
// adj0=exp(-(0.6d^2+0.2)) > 0 iff |d| <= 12. (verified: rel_err 8.5e-8)
#define DBAND 12

// -------- device global scratch --------
__device__ float g_xr[(size_t)NROWS * CC];          // [BN,T,C]
__device__ float g_h [(size_t)NROWS * CC];          // [BN,T,C] heads concat
__device__ float g_y [(size_t)NROWS * CC];          // pre-LN result
__device__ float2 g_stats[NROWS];                   // (mu, rstd)
__device__ unsigned long long g_sel[BN];            // top-k union mask bits

// -------- helpers --------
__device__ __forceinline__ uint32_t f2tf32(float x) {
    uint32_t r;
    asm("cvt.rna.tf32.f32 %0, %1;" : "=r"(r) : "f"(x));
    return r;
}
__device__ __forceinline__ void mma_tf32(float c[4], const uint32_t a[4], const uint32_t b[2]) {
    asm volatile(
        "mma.sync.aligned.m16n8k8.row.col.f32.tf32.tf32.f32 "
        "{%0,%1,%2,%3}, {%4,%5,%6,%7}, {%8,%9}, {%0,%1,%2,%3};"
        : "+f"(c[0]), "+f"(c[1]), "+f"(c[2]), "+f"(c[3])
        : "r"(a[0]), "r"(a[1]), "r"(a[2]), "r"(a[3]), "r"(b[0]), "r"(b[1]));
}

// -------- kernel 1: transpose x[B,T,C,HW] -> xr[BN,T,C] --------
__global__ void transpose_in_kernel(const float* __restrict__ x) {
    __shared__ float tile[32][33];
    int bt = blockIdx.z;                  // b*64+t
    int n0 = blockIdx.x * 32;
    int c0 = blockIdx.y * 32;
    int tx = threadIdx.x, ty = threadIdx.y;
    int b = bt >> 6, t = bt & 63;
#pragma unroll
    for (int i = 0; i < 4; i++) {
        int cl = ty + i * 8;
        int n = n0 + tx;
        if (n < HW)
            tile[cl][tx] = x[((size_t)bt * CC + (c0 + cl)) * HW + n];
    }
    __syncthreads();
#pragma unroll
    for (int i = 0; i < 4; i++) {
        int nl = ty + i * 8;
        int n = n0 + nl;
        if (n < HW)
            g_xr[(((size_t)(b * HW + n)) * TT + t) * CC + c0 + tx] = tile[tx][nl];
    }
}

// -------- kernel 2: per-bn top-k selection mask --------
__global__ __launch_bounds__(256) void sel_kernel() {
    __shared__ float magp[64][5];
    __shared__ float smag[64];
    __shared__ unsigned long long mparts[2];
    const int bn = blockIdx.x;
    const int tid = threadIdx.x;
    const float* __restrict__ slab = g_xr + (size_t)bn * TT * CC;
    {
        int t = tid >> 2, q = tid & 3;
        float s = 0.f;
        const float* p = slab + (size_t)t * CC + q * 128;
#pragma unroll 8
        for (int c = 0; c < 128; c++) { float v = p[c]; s = fmaf(v, v, s); }
        magp[t][q] = s;
    }
    __syncthreads();
    if (tid < 64)
        smag[tid] = sqrtf(magp[tid][0] + magp[tid][1] + magp[tid][2] + magp[tid][3]);
    __syncthreads();
    if (tid < 64) {
        float m = smag[tid];
        int rank = 0;
#pragma unroll 8
        for (int s = 0; s < 64; s++) {
            float ms = smag[s];
            rank += (ms > m) || (ms == m && s < tid);
        }
        unsigned bal = __ballot_sync(~0u, rank < KTOP);
        if ((tid & 31) == 0) mparts[tid >> 5] = bal;
    }
    __syncthreads();
    if (tid == 0) g_sel[bn] = mparts[0] | (mparts[1] << 32);
}

// -------- tf32 tensor-core GEMM: 128x64 tile, 8 warps (4m x 2n), 32x32/warp --------
// MODE 0: g_h = g_xr @ Wg[head]      (blockIdx.y = head, B = Wg + head*512*64, ldb=64)
// MODE 1: g_y = tmp @ W2 + b2 + g_xr (blockIdx.y = n-tile, ldb=512)
template <int MODE>
__global__ __launch_bounds__(256) void gemm_tf32_kernel(
    const float* __restrict__ Atmp, const float* __restrict__ Bsrc,
    const float* __restrict__ bias) {
    __shared__ float As[128][36];     // stride 36: frag banks 4g+t -> conflict-free
    __shared__ float Bs[32][72];      // stride 72: frag banks 8t+g -> conflict-free
    const int tid = threadIdx.x;
    const int m0 = blockIdx.x * 128;
    const int nt = blockIdx.y;                        // head (MODE0) or n-tile (MODE1)
    const float* __restrict__ A = (MODE == 0) ? g_xr : Atmp;
    const float* __restrict__ Bp = (MODE == 0) ? (Bsrc + (size_t)nt * CC * DH) : (Bsrc + nt * 64);
    const int ldb = (MODE == 0) ? DH : CC;

    const int lane = tid & 31, warp = tid >> 5;
    const int gid = lane >> 2, tq = lane & 3;
    const int wm = (warp >> 1) * 32, wn = (warp & 1) * 32;
    // staging roles
    const int sar = tid >> 3, sac = tid & 7;          // A: 32 row-groups x 8 float4 cols
    const int sbr = tid >> 4, sbc = tid & 15;         // B: 16 row-groups x 16 float4 cols

    float acc[2][4][4] = {};
    for (int k0 = 0; k0 < 512; k0 += 32) {
        // stage A: 128 x 32
#pragma unroll
        for (int i = 0; i < 4; i++) {
            int r = sar + i * 32;
            float4 v = *reinterpret_cast<const float4*>(&A[(size_t)(m0 + r) * CC + k0 + sac * 4]);
            uint4 w = make_uint4(f2tf32(v.x), f2tf32(v.y), f2tf32(v.z), f2tf32(v.w));
            *reinterpret_cast<uint4*>(&As[r][sac * 4]) = w;
        }
        // stage B: 32 x 64
#pragma unroll
        for (int i = 0; i < 2; i++) {
            int r = sbr + i * 16;
            float4 v = *reinterpret_cast<const float4*>(&Bp[(size_t)(k0 + r) * ldb + sbc * 4]);
            uint4 w = make_uint4(f2tf32(v.x), f2tf32(v.y), f2tf32(v.z), f2tf32(v.w));
            *reinterpret_cast<uint4*>(&Bs[r][sbc * 4]) = w;
        }
        __syncthreads();
#pragma unroll
        for (int ks = 0; ks < 4; ks++) {
            const int k = ks * 8;
            uint32_t af[2][4];
#pragma unroll
            for (int mi = 0; mi < 2; mi++) {
                int base = wm + mi * 16;
                af[mi][0] = __float_as_uint(As[base + gid][k + tq]);
                af[mi][1] = __float_as_uint(As[base + gid + 8][k + tq]);
                af[mi][2] = __float_as_uint(As[base + gid][k + tq + 4]);
                af[mi][3] = __float_as_uint(As[base + gid + 8][k + tq + 4]);
            }
            uint32_t bf[4][2];
#pragma unroll
            for (int ni = 0; ni < 4; ni++) {
                int n = wn + ni * 8 + gid;
                bf[ni][0] = __float_as_uint(Bs[k + tq][n]);
                bf[ni][1] = __float_as_uint(Bs[k + tq + 4][n]);
            }
#pragma unroll
            for (int mi = 0; mi < 2; mi++)
#pragma unroll
                for (int ni = 0; ni < 4; ni++)
                    mma_tf32(acc[mi][ni], af[mi], bf[ni]);
        }
        __syncthreads();
    }
    // epilogue: c0:(gid, tq*2) c1:+1 c2:(gid+8, tq*2) c3:+1
    const int ncol0 = nt * 64;
#pragma unroll
    for (int mi = 0; mi < 2; mi++) {
#pragma unroll
        for (int ni = 0; ni < 4; ni++) {
            int r0 = m0 + wm + mi * 16 + gid;
            int cc = ncol0 + wn + ni * 8 + tq * 2;
            float* c = acc[mi][ni];
            if (MODE == 0) {
                *reinterpret_cast<float2*>(&g_h[(size_t)r0 * CC + cc]) = make_float2(c[0], c[1]);
                *reinterpret_cast<float2*>(&g_h[(size_t)(r0 + 8) * CC + cc]) = make_float2(c[2], c[3]);
            } else {
                float2 bv = *reinterpret_cast<const float2*>(&bias[cc]);
                float2 x0 = *reinterpret_cast<const float2*>(&g_xr[(size_t)r0 * CC + cc]);
                float2 x1 = *reinterpret_cast<const float2*>(&g_xr[(size_t)(r0 + 8) * CC + cc]);
                *reinterpret_cast<float2*>(&g_y[(size_t)r0 * CC + cc]) =
                    make_float2(c[0] + bv.x + x0.x, c[1] + bv.y + x0.y);
                *reinterpret_cast<float2*>(&g_y[(size_t)(r0 + 8) * CC + cc]) =
                    make_float2(c[2] + bv.x + x1.x, c[3] + bv.y + x1.y);
            }
        }
    }
}

// -------- kernel 4: attention per (bn, head): softmax + att@h + ELU + sqrt + norm --------
__global__ __launch_bounds__(256) void attn2_kernel(
    const float* __restrict__ a1g, const float* __restrict__ a2g,
    float* __restrict__ tmp_out) {
    __shared__ float hh[64][68];
    __shared__ float att[64][68];
    __shared__ float f1[64], f2[64];
    __shared__ float sa1[64], sa2[64];

    const int bn = blockIdx.x;
    const int head = blockIdx.y;
    const int tid = threadIdx.x;
    const unsigned long long mask = g_sel[bn];
    const float* __restrict__ hbase = g_h + (size_t)bn * TT * CC + head * DH;

    // load h tile (float4 rows)
    {
        int r = tid >> 2, c0 = (tid & 3) * 4;
#pragma unroll
        for (int i = 0; i < 4; i++) {
            *reinterpret_cast<float4*>(&hh[r][c0 + i * 16]) =
                *reinterpret_cast<const float4*>(&hbase[(size_t)r * CC + c0 + i * 16]);
        }
    }
    if (tid < 64)       sa1[tid]      = a1g[head * DH + tid];
    else if (tid < 128) sa2[tid - 64] = a2g[head * DH + (tid - 64)];
    __syncthreads();

    if (tid < 64) {
        float s1 = 0.f, s2 = 0.f;
#pragma unroll 16
        for (int d = 0; d < 64; d++) {
            float hv = hh[tid][d];
            s1 = fmaf(hv, sa1[d], s1);
            s2 = fmaf(hv, sa2[d], s2);
        }
        f1[tid] = s1; f2[tid] = s2;
    }
    __syncthreads();

    const int warp = tid >> 5, lane = tid & 31;
    for (int t = warp; t < 64; t += 8) {
        int selt = (int)((mask >> t) & 1ull);
        float ft = f1[t];
        int s0 = lane, s1i = lane + 32;
        float e0 = ft + f2[s0];
        float e1 = ft + f2[s1i];
        e0 = fmaxf(e0, ALPHA * e0);
        e1 = fmaxf(e1, ALPHA * e1);
        bool m0v = (selt | (int)((mask >> s0) & 1ull))  && (abs(t - s0)  <= DBAND);
        bool m1v = (selt | (int)((mask >> s1i) & 1ull)) && (abs(t - s1i) <= DBAND);
        float l0 = m0v ? e0 : -9e15f;
        float l1 = m1v ? e1 : -9e15f;
        float mx = fmaxf(l0, l1);
#pragma unroll
        for (int o = 16; o; o >>= 1) mx = fmaxf(mx, __shfl_xor_sync(~0u, mx, o));
        float p0 = __expf(l0 - mx), p1 = __expf(l1 - mx);
        float sumv = p0 + p1;
#pragma unroll
        for (int o = 16; o; o >>= 1) sumv += __shfl_xor_sync(~0u, sumv, o);
        float inv = 1.f / sumv;
        att[t][s0]  = p0 * inv;
        att[t][s1i] = p1 * inv;
    }
    __syncthreads();

    const int t4 = (tid >> 4) * 4, d4 = (tid & 15) * 4;
    float acc2[4][4] = {};
    for (int s = 0; s < 64; s++) {
        float4 hv = *reinterpret_cast<const float4*>(&hh[s][d4]);
        float hb[4] = {hv.x, hv.y, hv.z, hv.w};
#pragma unroll
        for (int i = 0; i < 4; i++) {
            float a = att[t4 + i][s];
#pragma unroll
            for (int j = 0; j < 4; j++) acc2[i][j] = fmaf(a, hb[j], acc2[i][j]);
        }
    }
    float sv[4][4];
    float part[4] = {0.f, 0.f, 0.f, 0.f};
#pragma unroll
    for (int i = 0; i < 4; i++)
#pragma unroll
        for (int j = 0; j < 4; j++) {
            float v = acc2[i][j];
            float e = v > 0.f ? v : expm1f(v);
            float ae = fabsf(e);
            sv[i][j] = copysignf(sqrtf(ae), e);
            part[j] += ae;
        }
    __syncthreads();
#pragma unroll
    for (int j = 0; j < 4; j++) att[tid >> 4][d4 + j] = part[j];
    __syncthreads();
    if (tid < 64) {
        float tot = 0.f;
#pragma unroll
        for (int g = 0; g < 16; g++) tot += att[g][tid];
        f1[tid] = 1.f / fmaxf(sqrtf(tot), 1e-12f);
    }
    __syncthreads();
#pragma unroll
    for (int i = 0; i < 4; i++) {
        float4 o4 = make_float4(sv[i][0] * f1[d4 + 0], sv[i][1] * f1[d4 + 1],
                                sv[i][2] * f1[d4 + 2], sv[i][3] * f1[d4 + 3]);
        *reinterpret_cast<float4*>(
            &tmp_out[(size_t)bn * TT * CC + (size_t)(t4 + i) * CC + head * DH + d4]) = o4;
    }
}

// -------- kernel 5: LayerNorm stats per row --------
__global__ void ln_stats_kernel() {
    int row = blockIdx.x;
    const float* p = g_y + (size_t)row * CC;
    float s = 0.f, sq = 0.f;
    for (int c = threadIdx.x; c < CC; c += 128) {
        float v = p[c];
        s += v; sq = fmaf(v, v, sq);
    }
#pragma unroll
    for (int o = 16; o; o >>= 1) {
        s  += __shfl_xor_sync(~0u, s, o);
        sq += __shfl_xor_sync(~0u, sq, o);
    }
    __shared__ float rs[4], rq[4];
    if ((threadIdx.x & 31) == 0) { rs[threadIdx.x >> 5] = s; rq[threadIdx.x >> 5] = sq; }
    __syncthreads();
    if (threadIdx.x == 0) {
        float tot = rs[0] + rs[1] + rs[2] + rs[3];
        float totq = rq[0] + rq[1] + rq[2] + rq[3];
        float mu = tot * (1.f / CC);
        float var = totq * (1.f / CC) - mu * mu;
        g_stats[row] = make_float2(mu, rsqrtf(var + 1e-5f));
    }
}

// -------- kernel 6: apply LN + transpose back to [B,T,C,HW] --------
__global__ void transpose_out_kernel(const float* __restrict__ ln_g,
                                     const float* __restrict__ ln_b,
                                     float* __restrict__ out) {
    __shared__ float tile[32][33];
    int bt = blockIdx.z;
    int n0 = blockIdx.x * 32;
    int c0 = blockIdx.y * 32;
    int tx = threadIdx.x, ty = threadIdx.y;
    int b = bt >> 6, t = bt & 63;
    float lg = ln_g[c0 + tx], lb = ln_b[c0 + tx];
#pragma unroll
    for (int i = 0; i < 4; i++) {
        int nl = ty + i * 8;
        int n = n0 + nl;
        if (n < HW) {
            int bn = b * HW + n;
            float2 st = g_stats[bn * TT + t];
            float v = g_y[(((size_t)bn) * TT + t) * CC + c0 + tx];
            tile[nl][tx] = (v - st.x) * st.y * lg + lb;
        }
    }
    __syncthreads();
#pragma unroll
    for (int i = 0; i < 4; i++) {
        int cl = ty + i * 8;
        int n = n0 + tx;
        if (n < HW)
            out[((size_t)bt * CC + (c0 + cl)) * HW + n] = tile[tx][cl];
    }
}

extern "C" void kernel_launch(void* const* d_in, const int* in_sizes, int n_in,
                              void* d_out, int out_size) {
    const float* x    = (const float*)d_in[0];
    const float* Wg   = (const float*)d_in[1];
    const float* a1   = (const float*)d_in[2];
    const float* a2   = (const float*)d_in[3];
    const float* W2   = (const float*)d_in[4];
    const float* b2   = (const float*)d_in[5];
    const float* ln_g = (const float*)d_in[6];
    const float* ln_b = (const float*)d_in[7];
    float* out = (float*)d_out;

    transpose_in_kernel<<<dim3(7, 16, BB * TT), dim3(32, 8)>>>(x);
    sel_kernel<<<BN, 256>>>();
    gemm_tf32_kernel<0><<<dim3(NROWS / 128, 8), 256>>>(nullptr, Wg, nullptr);
    attn2_kernel<<<dim3(BN, NH), 256>>>(a1, a2, out);   // tmp -> d_out (overwritten later)
    gemm_tf32_kernel<1><<<dim3(NROWS / 128, 8), 256>>>(out, W2, b2);
    ln_stats_kernel<<<NROWS, 128>>>();
    transpose_out_kernel<<<dim3(7, 16, BB * TT), dim3(32, 8)>>>(ln_g, ln_b, out);
}

// round 14
// speedup vs baseline: 2.6676x; 1.1880x over previous
#include <cuda_runtime.h>
#include <math.h>
#include <stdint.h>

// Problem constants
#define BB 4
#define TT 64
#define CC 512
#define HW 196          // 14*14 spatial positions
#define BN (BB*HW)      // 784
#define NROWS (BN*TT)   // 50176
#define NH 8
#define DH 64
#define KTOP 19         // int(0.3*64)
#define ALPHA 0.2f
// DistanceAdj band: reference's Eigen pexp flushes subnormal outputs ->
// adj0=exp(-(0.6d^2+0.2)) > 0 iff |d| <= 12. (verified: rel_err 8.5e-8 fp32)
#define DBAND 12

// -------- device global scratch --------
__device__ float g_xr[(size_t)NROWS * CC];          // [BN,T,C]
__device__ float g_h [(size_t)NROWS * CC];          // [BN,T,C] heads concat
__device__ float g_y [(size_t)NROWS * CC];          // pre-LN result
__device__ float2 g_stats[NROWS];                   // (mu, rstd)
__device__ unsigned long long g_sel[BN];            // top-k union mask bits
__device__ float g_magp[(size_t)NROWS * 16];        // per-row sumsq partials (16 c-blocks)
__device__ float2 g_lnp[(size_t)NROWS * 8];         // per-row (sum,sumsq) partials (8 n-tiles)

// -------- helpers --------
__device__ __forceinline__ uint32_t f2tf32(float x) {
    uint32_t r;
    asm("cvt.rna.tf32.f32 %0, %1;" : "=r"(r) : "f"(x));
    return r;
}
__device__ __forceinline__ void mma_tf32(float c[4], const uint32_t a[4], const uint32_t b[2]) {
    asm volatile(
        "mma.sync.aligned.m16n8k8.row.col.f32.tf32.tf32.f32 "
        "{%0,%1,%2,%3}, {%4,%5,%6,%7}, {%8,%9}, {%0,%1,%2,%3};"
        : "+f"(c[0]), "+f"(c[1]), "+f"(c[2]), "+f"(c[3])
        : "r"(a[0]), "r"(a[1]), "r"(a[2]), "r"(a[3]), "r"(b[0]), "r"(b[1]));
}

// -------- kernel 1: transpose x -> xr, emitting sumsq partials --------
__global__ void transpose_in_kernel(const float* __restrict__ x) {
    __shared__ float tile[32][33];
    __shared__ float red[8][33];
    int bt = blockIdx.z;                  // b*64+t
    int n0 = blockIdx.x * 32;
    int c0 = blockIdx.y * 32;
    int tx = threadIdx.x, ty = threadIdx.y;
    int b = bt >> 6, t = bt & 63;
    float part = 0.f;
#pragma unroll
    for (int i = 0; i < 4; i++) {
        int cl = ty + i * 8;
        int n = n0 + tx;
        if (n < HW) {
            float v = x[((size_t)bt * CC + (c0 + cl)) * HW + n];
            tile[cl][tx] = v;
            part = fmaf(v, v, part);
        }
    }
    red[ty][tx] = part;
    __syncthreads();
#pragma unroll
    for (int i = 0; i < 4; i++) {
        int nl = ty + i * 8;
        int n = n0 + nl;
        if (n < HW)
            g_xr[(((size_t)(b * HW + n)) * TT + t) * CC + c0 + tx] = tile[tx][nl];
    }
    if (ty == 0) {
        int n = n0 + tx;
        if (n < HW) {
            float s = 0.f;
#pragma unroll
            for (int r = 0; r < 8; r++) s += red[r][tx];
            g_magp[(((size_t)(b * HW + n)) * TT + t) * 16 + blockIdx.y] = s;
        }
    }
}

// -------- kernel 2: per-bn top-k mask from sumsq partials (64 threads) --------
__global__ void sel2_kernel() {
    __shared__ float m2[64];
    __shared__ unsigned long long mparts[2];
    const int bn = blockIdx.x;
    const int tid = threadIdx.x;   // 0..63
    {
        const float* p = g_magp + ((size_t)bn * TT + tid) * 16;
        float s = 0.f;
#pragma unroll
        for (int i = 0; i < 16; i++) s += p[i];
        m2[tid] = s;               // sumsq; sqrt is monotone -> same ranks
    }
    __syncthreads();
    float m = m2[tid];
    int rank = 0;
#pragma unroll 8
    for (int s = 0; s < 64; s++) {
        float ms = m2[s];
        rank += (ms > m) || (ms == m && s < tid);
    }
    unsigned bal = __ballot_sync(~0u, rank < KTOP);
    if ((tid & 31) == 0) mparts[tid >> 5] = bal;
    __syncthreads();
    if (tid == 0) g_sel[bn] = mparts[0] | (mparts[1] << 32);
}

// -------- tf32 tensor-core GEMM: 128x64 tile, 8 warps (4m x 2n), 32x32/warp --------
// MODE 0: g_h = g_xr @ Wg[head]      (blockIdx.y = head, ldb=64)
// MODE 1: g_y = tmp @ W2 + b2 + g_xr (blockIdx.y = n-tile, ldb=512) + LN partials
template <int MODE>
__global__ __launch_bounds__(256) void gemm_tf32_kernel(
    const float* __restrict__ Atmp, const float* __restrict__ Bsrc,
    const float* __restrict__ bias) {
    __shared__ float As[128][36];
    __shared__ float Bs[32][72];
    __shared__ float lsum[128][2], lsq[128][2];   // MODE1 LN partials
    const int tid = threadIdx.x;
    const int m0 = blockIdx.x * 128;
    const int nt = blockIdx.y;
    const float* __restrict__ A = (MODE == 0) ? g_xr : Atmp;
    const float* __restrict__ Bp = (MODE == 0) ? (Bsrc + (size_t)nt * CC * DH) : (Bsrc + nt * 64);
    const int ldb = (MODE == 0) ? DH : CC;

    const int lane = tid & 31, warp = tid >> 5;
    const int gid = lane >> 2, tq = lane & 3;
    const int wm = (warp >> 1) * 32, wn = (warp & 1) * 32;
    const int sar = tid >> 3, sac = tid & 7;
    const int sbr = tid >> 4, sbc = tid & 15;

    float acc[2][4][4] = {};
    for (int k0 = 0; k0 < 512; k0 += 32) {
#pragma unroll
        for (int i = 0; i < 4; i++) {
            int r = sar + i * 32;
            float4 v = *reinterpret_cast<const float4*>(&A[(size_t)(m0 + r) * CC + k0 + sac * 4]);
            uint4 w = make_uint4(f2tf32(v.x), f2tf32(v.y), f2tf32(v.z), f2tf32(v.w));
            *reinterpret_cast<uint4*>(&As[r][sac * 4]) = w;
        }
#pragma unroll
        for (int i = 0; i < 2; i++) {
            int r = sbr + i * 16;
            float4 v = *reinterpret_cast<const float4*>(&Bp[(size_t)(k0 + r) * ldb + sbc * 4]);
            uint4 w = make_uint4(f2tf32(v.x), f2tf32(v.y), f2tf32(v.z), f2tf32(v.w));
            *reinterpret_cast<uint4*>(&Bs[r][sbc * 4]) = w;
        }
        __syncthreads();
#pragma unroll
        for (int ks = 0; ks < 4; ks++) {
            const int k = ks * 8;
            uint32_t af[2][4];
#pragma unroll
            for (int mi = 0; mi < 2; mi++) {
                int base = wm + mi * 16;
                af[mi][0] = __float_as_uint(As[base + gid][k + tq]);
                af[mi][1] = __float_as_uint(As[base + gid + 8][k + tq]);
                af[mi][2] = __float_as_uint(As[base + gid][k + tq + 4]);
                af[mi][3] = __float_as_uint(As[base + gid + 8][k + tq + 4]);
            }
            uint32_t bf[4][2];
#pragma unroll
            for (int ni = 0; ni < 4; ni++) {
                int n = wn + ni * 8 + gid;
                bf[ni][0] = __float_as_uint(Bs[k + tq][n]);
                bf[ni][1] = __float_as_uint(Bs[k + tq + 4][n]);
            }
#pragma unroll
            for (int mi = 0; mi < 2; mi++)
#pragma unroll
                for (int ni = 0; ni < 4; ni++)
                    mma_tf32(acc[mi][ni], af[mi], bf[ni]);
        }
        __syncthreads();
    }

    const int ncol0 = nt * 64;
    if (MODE == 0) {
#pragma unroll
        for (int mi = 0; mi < 2; mi++)
#pragma unroll
            for (int ni = 0; ni < 4; ni++) {
                int r0 = m0 + wm + mi * 16 + gid;
                int cc = ncol0 + wn + ni * 8 + tq * 2;
                float* c = acc[mi][ni];
                *reinterpret_cast<float2*>(&g_h[(size_t)r0 * CC + cc]) = make_float2(c[0], c[1]);
                *reinterpret_cast<float2*>(&g_h[(size_t)(r0 + 8) * CC + cc]) = make_float2(c[2], c[3]);
            }
    } else {
        float rs[2][2] = {}, rq[2][2] = {};   // [mi][half]
#pragma unroll
        for (int mi = 0; mi < 2; mi++)
#pragma unroll
            for (int ni = 0; ni < 4; ni++) {
                int r0 = m0 + wm + mi * 16 + gid;
                int cc = ncol0 + wn + ni * 8 + tq * 2;
                float* c = acc[mi][ni];
                float2 bv = *reinterpret_cast<const float2*>(&bias[cc]);
                float2 x0 = *reinterpret_cast<const float2*>(&g_xr[(size_t)r0 * CC + cc]);
                float2 x1 = *reinterpret_cast<const float2*>(&g_xr[(size_t)(r0 + 8) * CC + cc]);
                float y0x = c[0] + bv.x + x0.x, y0y = c[1] + bv.y + x0.y;
                float y1x = c[2] + bv.x + x1.x, y1y = c[3] + bv.y + x1.y;
                *reinterpret_cast<float2*>(&g_y[(size_t)r0 * CC + cc]) = make_float2(y0x, y0y);
                *reinterpret_cast<float2*>(&g_y[(size_t)(r0 + 8) * CC + cc]) = make_float2(y1x, y1y);
                rs[mi][0] += y0x + y0y; rq[mi][0] = fmaf(y0x, y0x, fmaf(y0y, y0y, rq[mi][0]));
                rs[mi][1] += y1x + y1y; rq[mi][1] = fmaf(y1x, y1x, fmaf(y1y, y1y, rq[mi][1]));
            }
        // reduce cols over quad (tq) — rows identical within quad
#pragma unroll
        for (int o = 1; o <= 2; o <<= 1)
#pragma unroll
            for (int mi = 0; mi < 2; mi++)
#pragma unroll
                for (int h = 0; h < 2; h++) {
                    rs[mi][h] += __shfl_xor_sync(~0u, rs[mi][h], o);
                    rq[mi][h] += __shfl_xor_sync(~0u, rq[mi][h], o);
                }
        if (tq == 0) {
#pragma unroll
            for (int mi = 0; mi < 2; mi++)
#pragma unroll
                for (int h = 0; h < 2; h++) {
                    int rl = wm + mi * 16 + gid + h * 8;
                    lsum[rl][warp & 1] = rs[mi][h];
                    lsq [rl][warp & 1] = rq[mi][h];
                }
        }
        __syncthreads();
        if (tid < 128) {
            float s = lsum[tid][0] + lsum[tid][1];
            float q = lsq [tid][0] + lsq [tid][1];
            g_lnp[(size_t)(m0 + tid) * 8 + nt] = make_float2(s, q);
        }
    }
}

// -------- kernel 4: attention per (bn, head), tensor-core att@h --------
__global__ __launch_bounds__(256) void attn2_kernel(
    const float* __restrict__ a1g, const float* __restrict__ a2g,
    float* __restrict__ tmp_out) {
    __shared__ float hh[64][68];     // h (tf32-rounded); later reused for sv
    __shared__ float att[64][68];    // softmax matrix (tf32-rounded)
    __shared__ float f1[64], f2[64]; // logits; f1 later reused as inv col norm
    __shared__ float sa1[64], sa2[64];
    __shared__ float colp[4][64];

    const int bn = blockIdx.x;
    const int head = blockIdx.y;
    const int tid = threadIdx.x;
    const unsigned long long mask = g_sel[bn];
    const float* __restrict__ hbase = g_h + (size_t)bn * TT * CC + head * DH;

    // load h tile, round to tf32 once (used for f1/f2, mma B, and output V)
    {
        int r = tid >> 2, c0 = (tid & 3) * 4;
#pragma unroll
        for (int i = 0; i < 4; i++) {
            float4 v = *reinterpret_cast<const float4*>(&hbase[(size_t)r * CC + c0 + i * 16]);
            hh[r][c0 + i * 16 + 0] = __uint_as_float(f2tf32(v.x));
            hh[r][c0 + i * 16 + 1] = __uint_as_float(f2tf32(v.y));
            hh[r][c0 + i * 16 + 2] = __uint_as_float(f2tf32(v.z));
            hh[r][c0 + i * 16 + 3] = __uint_as_float(f2tf32(v.w));
        }
    }
    if (tid < 64)       sa1[tid]      = a1g[head * DH + tid];
    else if (tid < 128) sa2[tid - 64] = a2g[head * DH + (tid - 64)];
    __syncthreads();

    if (tid < 128) {
        int t = tid & 63;
        const float* w = (tid < 64) ? sa1 : sa2;
        float s = 0.f;
#pragma unroll 16
        for (int d = 0; d < 64; d++) s = fmaf(hh[t][d], w[d], s);
        if (tid < 64) f1[t] = s; else f2[t] = s;
    }
    __syncthreads();

    const int warp = tid >> 5, lane = tid & 31;
    for (int t = warp; t < 64; t += 8) {
        int selt = (int)((mask >> t) & 1ull);
        float ft = f1[t];
        int s0 = lane, s1i = lane + 32;
        float e0 = ft + f2[s0];
        float e1 = ft + f2[s1i];
        e0 = fmaxf(e0, ALPHA * e0);
        e1 = fmaxf(e1, ALPHA * e1);
        bool m0v = (selt | (int)((mask >> s0) & 1ull))  && (abs(t - s0)  <= DBAND);
        bool m1v = (selt | (int)((mask >> s1i) & 1ull)) && (abs(t - s1i) <= DBAND);
        float l0 = m0v ? e0 : -9e15f;
        float l1 = m1v ? e1 : -9e15f;
        float mx = fmaxf(l0, l1);
#pragma unroll
        for (int o = 16; o; o >>= 1) mx = fmaxf(mx, __shfl_xor_sync(~0u, mx, o));
        float p0 = __expf(l0 - mx), p1 = __expf(l1 - mx);
        float sumv = p0 + p1;
#pragma unroll
        for (int o = 16; o; o >>= 1) sumv += __shfl_xor_sync(~0u, sumv, o);
        float inv = 1.f / sumv;
        att[t][s0]  = __uint_as_float(f2tf32(p0 * inv));
        att[t][s1i] = __uint_as_float(f2tf32(p1 * inv));
    }
    __syncthreads();

    // D[64x64] = att @ hh via tf32 mma: warp (wm,wn): rows wm*16..+16, cols wn*32..+32
    const int gid = lane >> 2, tq = lane & 3;
    const int wm = warp & 3, wn = warp >> 2;
    float acc[4][4] = {};
#pragma unroll
    for (int k0 = 0; k0 < 64; k0 += 8) {
        uint32_t af[4];
        af[0] = __float_as_uint(att[wm * 16 + gid][k0 + tq]);
        af[1] = __float_as_uint(att[wm * 16 + gid + 8][k0 + tq]);
        af[2] = __float_as_uint(att[wm * 16 + gid][k0 + tq + 4]);
        af[3] = __float_as_uint(att[wm * 16 + gid + 8][k0 + tq + 4]);
#pragma unroll
        for (int ni = 0; ni < 4; ni++) {
            int n = wn * 32 + ni * 8 + gid;
            uint32_t bf[2];
            bf[0] = __float_as_uint(hh[k0 + tq][n]);
            bf[1] = __float_as_uint(hh[k0 + tq + 4][n]);
            mma_tf32(acc[ni], af, bf);
        }
    }
    __syncthreads();   // all att/hh reads done; reuse hh for sv

    // ELU + signed-sqrt; stash sv in hh; per-column |elu| partials
    float colpart[8] = {};
#pragma unroll
    for (int ni = 0; ni < 4; ni++) {
        int R = wm * 16 + gid, C = wn * 32 + ni * 8 + tq * 2;
        float* c = acc[ni];
#pragma unroll
        for (int q = 0; q < 4; q++) {
            int r = R + (q >> 1) * 8, cc = C + (q & 1);
            float v = c[q];
            float e = v > 0.f ? v : expm1f(v);
            float ae = fabsf(e);
            hh[r][cc] = copysignf(sqrtf(ae), e);
            colpart[ni * 2 + (q & 1)] += ae;
        }
    }
#pragma unroll
    for (int o = 4; o <= 16; o <<= 1)
#pragma unroll
        for (int j = 0; j < 8; j++)
            colpart[j] += __shfl_xor_sync(~0u, colpart[j], o);
    if (gid == 0) {
#pragma unroll
        for (int ni = 0; ni < 4; ni++) {
            colp[wm][wn * 32 + ni * 8 + tq * 2]     = colpart[ni * 2];
            colp[wm][wn * 32 + ni * 8 + tq * 2 + 1] = colpart[ni * 2 + 1];
        }
    }
    __syncthreads();
    if (tid < 64) {
        float tot = colp[0][tid] + colp[1][tid] + colp[2][tid] + colp[3][tid];
        f1[tid] = 1.f / fmaxf(sqrtf(tot), 1e-12f);
    }
    __syncthreads();

    // scale + write tmp
    {
        int r = tid >> 2, c0 = (tid & 3) * 16;
        float* outp = tmp_out + (size_t)bn * TT * CC + (size_t)r * CC + head * DH;
#pragma unroll
        for (int i = 0; i < 4; i++) {
            int c = c0 + i * 4;
            float4 o4 = make_float4(hh[r][c] * f1[c], hh[r][c + 1] * f1[c + 1],
                                    hh[r][c + 2] * f1[c + 2], hh[r][c + 3] * f1[c + 3]);
            *reinterpret_cast<float4*>(&outp[c]) = o4;
        }
    }
}

// -------- kernel 5: finalize LN stats from partials --------
__global__ void ln_fin_kernel() {
    int row = blockIdx.x * 256 + threadIdx.x;
    if (row >= NROWS) return;
    const float2* p = g_lnp + (size_t)row * 8;
    float s = 0.f, q = 0.f;
#pragma unroll
    for (int i = 0; i < 8; i++) { float2 v = p[i]; s += v.x; q += v.y; }
    float mu = s * (1.f / CC);
    float var = q * (1.f / CC) - mu * mu;
    g_stats[row] = make_float2(mu, rsqrtf(var + 1e-5f));
}

// -------- kernel 6: apply LN + transpose back to [B,T,C,HW] --------
__global__ void transpose_out_kernel(const float* __restrict__ ln_g,
                                     const float* __restrict__ ln_b,
                                     float* __restrict__ out) {
    __shared__ float tile[32][33];
    int bt = blockIdx.z;
    int n0 = blockIdx.x * 32;
    int c0 = blockIdx.y * 32;
    int tx = threadIdx.x, ty = threadIdx.y;
    int b = bt >> 6, t = bt & 63;
    float lg = ln_g[c0 + tx], lb = ln_b[c0 + tx];
#pragma unroll
    for (int i = 0; i < 4; i++) {
        int nl = ty + i * 8;
        int n = n0 + nl;
        if (n < HW) {
            int bn = b * HW + n;
            float2 st = g_stats[bn * TT + t];
            float v = g_y[(((size_t)bn) * TT + t) * CC + c0 + tx];
            tile[nl][tx] = (v - st.x) * st.y * lg + lb;
        }
    }
    __syncthreads();
#pragma unroll
    for (int i = 0; i < 4; i++) {
        int cl = ty + i * 8;
        int n = n0 + tx;
        if (n < HW)
            out[((size_t)bt * CC + (c0 + cl)) * HW + n] = tile[tx][cl];
    }
}

extern "C" void kernel_launch(void* const* d_in, const int* in_sizes, int n_in,
                              void* d_out, int out_size) {
    const float* x    = (const float*)d_in[0];
    const float* Wg   = (const float*)d_in[1];
    const float* a1   = (const float*)d_in[2];
    const float* a2   = (const float*)d_in[3];
    const float* W2   = (const float*)d_in[4];
    const float* b2   = (const float*)d_in[5];
    const float* ln_g = (const float*)d_in[6];
    const float* ln_b = (const float*)d_in[7];
    float* out = (float*)d_out;

    transpose_in_kernel<<<dim3(7, 16, BB * TT), dim3(32, 8)>>>(x);
    sel2_kernel<<<BN, 64>>>();
    gemm_tf32_kernel<0><<<dim3(NROWS / 128, 8), 256>>>(nullptr, Wg, nullptr);
    attn2_kernel<<<dim3(BN, NH), 256>>>(a1, a2, out);   // tmp -> d_out
    gemm_tf32_kernel<1><<<dim3(NROWS / 128, 8), 256>>>(out, W2, b2);
    ln_fin_kernel<<<(NROWS + 255) / 256, 256>>>();
    transpose_out_kernel<<<dim3(7, 16, BB * TT), dim3(32, 8)>>>(ln_g, ln_b, out);
}

// round 15
// speedup vs baseline: 2.7201x; 1.0197x over previous
#include <cuda_runtime.h>
#include <math.h>
#include <stdint.h>

// Problem constants
#define BB 4
#define TT 64
#define CC 512
#define HW 196          // 14*14 spatial positions
#define BN (BB*HW)      // 784
#define NROWS (BN*TT)   // 50176
#define NH 8
#define DH 64
#define KTOP 19         // int(0.3*64)
#define ALPHA 0.2f
// DistanceAdj band: reference's Eigen pexp flushes subnormal outputs ->
// adj0=exp(-(0.6d^2+0.2)) > 0 iff |d| <= 12. (verified)
#define DBAND 12

// -------- device global scratch --------
__device__ float g_xr[(size_t)NROWS * CC];          // [BN,T,C]
__device__ float g_y [(size_t)NROWS * CC];          // pre-LN result
__device__ float2 g_stats[NROWS];                   // (mu, rstd)
__device__ unsigned long long g_sel[BN];            // top-k union mask bits
__device__ float g_magp[(size_t)NROWS * 16];        // per-row sumsq partials
__device__ float2 g_lnp[(size_t)NROWS * 8];         // per-row (sum,sumsq) partials

// -------- helpers --------
__device__ __forceinline__ uint32_t f2tf32(float x) {
    uint32_t r;
    asm("cvt.rna.tf32.f32 %0, %1;" : "=r"(r) : "f"(x));
    return r;
}
__device__ __forceinline__ void mma_tf32(float c[4], const uint32_t a[4], const uint32_t b[2]) {
    asm volatile(
        "mma.sync.aligned.m16n8k8.row.col.f32.tf32.tf32.f32 "
        "{%0,%1,%2,%3}, {%4,%5,%6,%7}, {%8,%9}, {%0,%1,%2,%3};"
        : "+f"(c[0]), "+f"(c[1]), "+f"(c[2]), "+f"(c[3])
        : "r"(a[0]), "r"(a[1]), "r"(a[2]), "r"(a[3]), "r"(b[0]), "r"(b[1]));
}

// -------- kernel 1: transpose x -> xr, emitting sumsq partials --------
__global__ void transpose_in_kernel(const float* __restrict__ x) {
    __shared__ float tile[32][33];
    __shared__ float red[8][33];
    int bt = blockIdx.z;                  // b*64+t
    int n0 = blockIdx.x * 32;
    int c0 = blockIdx.y * 32;
    int tx = threadIdx.x, ty = threadIdx.y;
    int b = bt >> 6, t = bt & 63;
    float part = 0.f;
#pragma unroll
    for (int i = 0; i < 4; i++) {
        int cl = ty + i * 8;
        int n = n0 + tx;
        if (n < HW) {
            float v = x[((size_t)bt * CC + (c0 + cl)) * HW + n];
            tile[cl][tx] = v;
            part = fmaf(v, v, part);
        }
    }
    red[ty][tx] = part;
    __syncthreads();
#pragma unroll
    for (int i = 0; i < 4; i++) {
        int nl = ty + i * 8;
        int n = n0 + nl;
        if (n < HW)
            g_xr[(((size_t)(b * HW + n)) * TT + t) * CC + c0 + tx] = tile[tx][nl];
    }
    if (ty == 0) {
        int n = n0 + tx;
        if (n < HW) {
            float s = 0.f;
#pragma unroll
            for (int r = 0; r < 8; r++) s += red[r][tx];
            g_magp[(((size_t)(b * HW + n)) * TT + t) * 16 + blockIdx.y] = s;
        }
    }
}

// -------- kernel 2: per-bn top-k mask from sumsq partials --------
__global__ void sel2_kernel() {
    __shared__ float m2[64];
    __shared__ unsigned long long mparts[2];
    const int bn = blockIdx.x;
    const int tid = threadIdx.x;   // 0..63
    {
        const float* p = g_magp + ((size_t)bn * TT + tid) * 16;
        float s = 0.f;
#pragma unroll
        for (int i = 0; i < 16; i++) s += p[i];
        m2[tid] = s;               // sumsq; sqrt monotone -> same ranks
    }
    __syncthreads();
    float m = m2[tid];
    int rank = 0;
#pragma unroll 8
    for (int s = 0; s < 64; s++) {
        float ms = m2[s];
        rank += (ms > m) || (ms == m && s < tid);
    }
    unsigned bal = __ballot_sync(~0u, rank < KTOP);
    if ((tid & 31) == 0) mparts[tid >> 5] = bal;
    __syncthreads();
    if (tid == 0) g_sel[bn] = mparts[0] | (mparts[1] << 32);
}

// ===== fused GAT: h-GEMM (tf32 mma) + attention for 2 bn x 1 head per block ====
// grid (392, 8); block 256; dynamic smem 73216B.
// smem layout: hh[128][68] | regB{ phase1: As[128][36],Bs[32][72]
//                                  phase2: att[128][68] } | f1p[128] f2p[128]
//                                  sa1[64] sa2[64] colp[8][64]
#define GAT_SMEM ((128*68 + 8704 + 128 + 128 + 64 + 64 + 512) * 4)

__global__ __launch_bounds__(256) void gat_fused_kernel(
    const float* __restrict__ Wg, const float* __restrict__ a1g,
    const float* __restrict__ a2g, float* __restrict__ tmp_out) {
    extern __shared__ float smf[];
    float (*hh)[68]  = reinterpret_cast<float(*)[68]>(smf);          // [128][68]
    float* regB = smf + 128 * 68;
    float (*As)[36]  = reinterpret_cast<float(*)[36]>(regB);
    float (*Bs)[72]  = reinterpret_cast<float(*)[72]>(regB + 128 * 36);
    float (*att)[68] = reinterpret_cast<float(*)[68]>(regB);         // [128][68]
    float* f1p  = regB + 8704;    // [128] logits f1; later inv col norms
    float* f2p  = f1p + 128;      // [128]
    float* sa1  = f2p + 128;      // [64]
    float* sa2  = sa1 + 64;       // [64]
    float* colp = sa2 + 64;       // [8][64] = (half*4+wl)*64 + c
    __shared__ unsigned long long smask[2];

    const int tid = threadIdx.x;
    const int m0 = blockIdx.x * 128;
    const int head = blockIdx.y;
    const int bn0 = blockIdx.x * 2;
    const int lane = tid & 31, warp = tid >> 5;
    const int gid = lane >> 2, tq = lane & 3;

    // non-conflicting smem regions: load early
    if (tid < 64)        sa1[tid]       = a1g[head * DH + tid];
    else if (tid < 128)  sa2[tid - 64]  = a2g[head * DH + (tid - 64)];
    else if (tid == 128) smask[0] = g_sel[bn0];
    else if (tid == 129) smask[1] = g_sel[bn0 + 1];

    // ---- phase 1: h-GEMM (proven tf32 mma structure) ----
    const float* __restrict__ Bp = Wg + (size_t)head * CC * DH;
    const int wm = (warp >> 1) * 32, wn = (warp & 1) * 32;
    const int sar = tid >> 3, sac = tid & 7;
    const int sbr = tid >> 4, sbc = tid & 15;

    float acc[2][4][4] = {};
    for (int k0 = 0; k0 < 512; k0 += 32) {
#pragma unroll
        for (int i = 0; i < 4; i++) {
            int r = sar + i * 32;
            float4 v = *reinterpret_cast<const float4*>(&g_xr[(size_t)(m0 + r) * CC + k0 + sac * 4]);
            uint4 w = make_uint4(f2tf32(v.x), f2tf32(v.y), f2tf32(v.z), f2tf32(v.w));
            *reinterpret_cast<uint4*>(&As[r][sac * 4]) = w;
        }
#pragma unroll
        for (int i = 0; i < 2; i++) {
            int r = sbr + i * 16;
            float4 v = *reinterpret_cast<const float4*>(&Bp[(size_t)(k0 + r) * DH + sbc * 4]);
            uint4 w = make_uint4(f2tf32(v.x), f2tf32(v.y), f2tf32(v.z), f2tf32(v.w));
            *reinterpret_cast<uint4*>(&Bs[r][sbc * 4]) = w;
        }
        __syncthreads();
#pragma unroll
        for (int ks = 0; ks < 4; ks++) {
            const int k = ks * 8;
            uint32_t af[2][4];
#pragma unroll
            for (int mi = 0; mi < 2; mi++) {
                int base = wm + mi * 16;
                af[mi][0] = __float_as_uint(As[base + gid][k + tq]);
                af[mi][1] = __float_as_uint(As[base + gid + 8][k + tq]);
                af[mi][2] = __float_as_uint(As[base + gid][k + tq + 4]);
                af[mi][3] = __float_as_uint(As[base + gid + 8][k + tq + 4]);
            }
            uint32_t bf[4][2];
#pragma unroll
            for (int ni = 0; ni < 4; ni++) {
                int n = wn + ni * 8 + gid;
                bf[ni][0] = __float_as_uint(Bs[k + tq][n]);
                bf[ni][1] = __float_as_uint(Bs[k + tq + 4][n]);
            }
#pragma unroll
            for (int mi = 0; mi < 2; mi++)
#pragma unroll
                for (int ni = 0; ni < 4; ni++)
                    mma_tf32(acc[mi][ni], af[mi], bf[ni]);
        }
        __syncthreads();
    }
    // store h tile (tf32-rounded once; used for f1/f2, mma-B, and V)
#pragma unroll
    for (int mi = 0; mi < 2; mi++)
#pragma unroll
        for (int ni = 0; ni < 4; ni++) {
            int r0 = wm + mi * 16 + gid;
            int c0 = wn + ni * 8 + tq * 2;
            float* c = acc[mi][ni];
            hh[r0][c0]         = __uint_as_float(f2tf32(c[0]));
            hh[r0][c0 + 1]     = __uint_as_float(f2tf32(c[1]));
            hh[r0 + 8][c0]     = __uint_as_float(f2tf32(c[2]));
            hh[r0 + 8][c0 + 1] = __uint_as_float(f2tf32(c[3]));
        }
    __syncthreads();

    // ---- phase 2: attention on two 64x64 tiles (warps 0-3 half0, 4-7 half1) ----
    // f1/f2 logits for all 128 rows
    {
        int row = tid & 127;
        const float* w = (tid < 128) ? sa1 : sa2;
        float s = 0.f;
#pragma unroll 16
        for (int d = 0; d < 64; d++) s = fmaf(hh[row][d], w[d], s);
        ((tid < 128) ? f1p : f2p)[row] = s;
    }
    __syncthreads();

    const int half = warp >> 2, wl = warp & 3;
    const unsigned long long selm = smask[half];
    // masked softmax: 4 warps per half, 16 rows each
    for (int t = wl; t < 64; t += 4) {
        unsigned long long band = (t >= DBAND) ? (0x1FFFFFFull << (t - DBAND))
                                               : (0x1FFFFFFull >> (DBAND - t));
        unsigned long long rowm = ((((selm >> t) & 1ull) ? ~0ull : selm)) & band;
        float ft = f1p[half * 64 + t];
        int s0 = lane, s1 = lane + 32;
        float e0 = ft + f2p[half * 64 + s0];
        float e1 = ft + f2p[half * 64 + s1];
        e0 = fmaxf(e0, ALPHA * e0);
        e1 = fmaxf(e1, ALPHA * e1);
        float l0 = ((rowm >> s0) & 1ull) ? e0 : -9e15f;
        float l1 = ((rowm >> s1) & 1ull) ? e1 : -9e15f;
        float mx = fmaxf(l0, l1);
#pragma unroll
        for (int o = 16; o; o >>= 1) mx = fmaxf(mx, __shfl_xor_sync(~0u, mx, o));
        float p0 = __expf(l0 - mx), p1 = __expf(l1 - mx);
        float sumv = p0 + p1;
#pragma unroll
        for (int o = 16; o; o >>= 1) sumv += __shfl_xor_sync(~0u, sumv, o);
        float inv = 1.f / sumv;
        att[half * 64 + t][s0] = __uint_as_float(f2tf32(p0 * inv));
        att[half * 64 + t][s1] = __uint_as_float(f2tf32(p1 * inv));
    }
    __syncthreads();

    // D = att @ hh per half: warp covers rows wl*16..+16, all 64 cols (8 ni)
    const int rbase = half * 64;
    float acc2[8][4] = {};
#pragma unroll
    for (int k0 = 0; k0 < 64; k0 += 8) {
        uint32_t af[4];
        af[0] = __float_as_uint(att[rbase + wl * 16 + gid][k0 + tq]);
        af[1] = __float_as_uint(att[rbase + wl * 16 + gid + 8][k0 + tq]);
        af[2] = __float_as_uint(att[rbase + wl * 16 + gid][k0 + tq + 4]);
        af[3] = __float_as_uint(att[rbase + wl * 16 + gid + 8][k0 + tq + 4]);
#pragma unroll
        for (int ni = 0; ni < 8; ni++) {
            int n = ni * 8 + gid;
            uint32_t bf[2];
            bf[0] = __float_as_uint(hh[rbase + k0 + tq][n]);
            bf[1] = __float_as_uint(hh[rbase + k0 + tq + 4][n]);
            mma_tf32(acc2[ni], af, bf);
        }
    }
    __syncthreads();   // all att/hh reads done; reuse hh for sv

    // ELU + signed-sqrt -> hh; per-column |elu| partials
    float cpart[16] = {};
#pragma unroll
    for (int ni = 0; ni < 8; ni++) {
        int r0 = rbase + wl * 16 + gid;
        int c0 = ni * 8 + tq * 2;
        float* c = acc2[ni];
#pragma unroll
        for (int q = 0; q < 4; q++) {
            int r = r0 + (q >> 1) * 8, cc = c0 + (q & 1);
            float v = c[q];
            float e = v > 0.f ? v : (__expf(v) - 1.f);
            float ae = fabsf(e);
            hh[r][cc] = copysignf(sqrtf(ae), e);
            cpart[ni * 2 + (q & 1)] += ae;
        }
    }
#pragma unroll
    for (int o = 4; o <= 16; o <<= 1)
#pragma unroll
        for (int j = 0; j < 16; j++)
            cpart[j] += __shfl_xor_sync(~0u, cpart[j], o);
    if (gid == 0) {
#pragma unroll
        for (int ni = 0; ni < 8; ni++) {
            colp[(half * 4 + wl) * 64 + ni * 8 + tq * 2]     = cpart[ni * 2];
            colp[(half * 4 + wl) * 64 + ni * 8 + tq * 2 + 1] = cpart[ni * 2 + 1];
        }
    }
    __syncthreads();
    if (tid < 128) {   // inverse column norms -> f1p (logits dead)
        int h = tid >> 6, c = tid & 63;
        float tot = colp[(h * 4 + 0) * 64 + c] + colp[(h * 4 + 1) * 64 + c]
                  + colp[(h * 4 + 2) * 64 + c] + colp[(h * 4 + 3) * 64 + c];
        f1p[tid] = 1.f / fmaxf(sqrtf(tot), 1e-12f);
    }
    __syncthreads();

    // scale + write tmp (coalesced: 16 lanes per row)
#pragma unroll
    for (int i = 0; i < 8; i++) {
        int r = (tid >> 4) + i * 16;          // 0..127
        int c4 = (tid & 15) * 4;
        int ib = (r >> 6) * 64;
        float4 o4 = make_float4(hh[r][c4]     * f1p[ib + c4],
                                hh[r][c4 + 1] * f1p[ib + c4 + 1],
                                hh[r][c4 + 2] * f1p[ib + c4 + 2],
                                hh[r][c4 + 3] * f1p[ib + c4 + 3]);
        int bn = bn0 + (r >> 6), t = r & 63;
        *reinterpret_cast<float4*>(
            &tmp_out[((size_t)bn * TT + t) * CC + head * DH + c4]) = o4;
    }
}

// -------- gemm1: g_y = tmp @ W2 + b2 + g_xr, with LN partials (proven) --------
__global__ __launch_bounds__(256) void gemm_out_kernel(
    const float* __restrict__ Atmp, const float* __restrict__ Bsrc,
    const float* __restrict__ bias) {
    __shared__ float As[128][36];
    __shared__ float Bs[32][72];
    __shared__ float lsum[128][2], lsq[128][2];
    const int tid = threadIdx.x;
    const int m0 = blockIdx.x * 128;
    const int nt = blockIdx.y;
    const float* __restrict__ Bp = Bsrc + nt * 64;

    const int lane = tid & 31, warp = tid >> 5;
    const int gid = lane >> 2, tq = lane & 3;
    const int wm = (warp >> 1) * 32, wn = (warp & 1) * 32;
    const int sar = tid >> 3, sac = tid & 7;
    const int sbr = tid >> 4, sbc = tid & 15;

    float acc[2][4][4] = {};
    for (int k0 = 0; k0 < 512; k0 += 32) {
#pragma unroll
        for (int i = 0; i < 4; i++) {
            int r = sar + i * 32;
            float4 v = *reinterpret_cast<const float4*>(&Atmp[(size_t)(m0 + r) * CC + k0 + sac * 4]);
            uint4 w = make_uint4(f2tf32(v.x), f2tf32(v.y), f2tf32(v.z), f2tf32(v.w));
            *reinterpret_cast<uint4*>(&As[r][sac * 4]) = w;
        }
#pragma unroll
        for (int i = 0; i < 2; i++) {
            int r = sbr + i * 16;
            float4 v = *reinterpret_cast<const float4*>(&Bp[(size_t)(k0 + r) * CC + sbc * 4]);
            uint4 w = make_uint4(f2tf32(v.x), f2tf32(v.y), f2tf32(v.z), f2tf32(v.w));
            *reinterpret_cast<uint4*>(&Bs[r][sbc * 4]) = w;
        }
        __syncthreads();
#pragma unroll
        for (int ks = 0; ks < 4; ks++) {
            const int k = ks * 8;
            uint32_t af[2][4];
#pragma unroll
            for (int mi = 0; mi < 2; mi++) {
                int base = wm + mi * 16;
                af[mi][0] = __float_as_uint(As[base + gid][k + tq]);
                af[mi][1] = __float_as_uint(As[base + gid + 8][k + tq]);
                af[mi][2] = __float_as_uint(As[base + gid][k + tq + 4]);
                af[mi][3] = __float_as_uint(As[base + gid + 8][k + tq + 4]);
            }
            uint32_t bf[4][2];
#pragma unroll
            for (int ni = 0; ni < 4; ni++) {
                int n = wn + ni * 8 + gid;
                bf[ni][0] = __float_as_uint(Bs[k + tq][n]);
                bf[ni][1] = __float_as_uint(Bs[k + tq + 4][n]);
            }
#pragma unroll
            for (int mi = 0; mi < 2; mi++)
#pragma unroll
                for (int ni = 0; ni < 4; ni++)
                    mma_tf32(acc[mi][ni], af[mi], bf[ni]);
        }
        __syncthreads();
    }

    const int ncol0 = nt * 64;
    float rs[2][2] = {}, rq[2][2] = {};
#pragma unroll
    for (int mi = 0; mi < 2; mi++)
#pragma unroll
        for (int ni = 0; ni < 4; ni++) {
            int r0 = m0 + wm + mi * 16 + gid;
            int cc = ncol0 + wn + ni * 8 + tq * 2;
            float* c = acc[mi][ni];
            float2 bv = *reinterpret_cast<const float2*>(&bias[cc]);
            float2 x0 = *reinterpret_cast<const float2*>(&g_xr[(size_t)r0 * CC + cc]);
            float2 x1 = *reinterpret_cast<const float2*>(&g_xr[(size_t)(r0 + 8) * CC + cc]);
            float y0x = c[0] + bv.x + x0.x, y0y = c[1] + bv.y + x0.y;
            float y1x = c[2] + bv.x + x1.x, y1y = c[3] + bv.y + x1.y;
            *reinterpret_cast<float2*>(&g_y[(size_t)r0 * CC + cc]) = make_float2(y0x, y0y);
            *reinterpret_cast<float2*>(&g_y[(size_t)(r0 + 8) * CC + cc]) = make_float2(y1x, y1y);
            rs[mi][0] += y0x + y0y; rq[mi][0] = fmaf(y0x, y0x, fmaf(y0y, y0y, rq[mi][0]));
            rs[mi][1] += y1x + y1y; rq[mi][1] = fmaf(y1x, y1x, fmaf(y1y, y1y, rq[mi][1]));
        }
#pragma unroll
    for (int o = 1; o <= 2; o <<= 1)
#pragma unroll
        for (int mi = 0; mi < 2; mi++)
#pragma unroll
            for (int h = 0; h < 2; h++) {
                rs[mi][h] += __shfl_xor_sync(~0u, rs[mi][h], o);
                rq[mi][h] += __shfl_xor_sync(~0u, rq[mi][h], o);
            }
    if (tq == 0) {
#pragma unroll
        for (int mi = 0; mi < 2; mi++)
#pragma unroll
            for (int h = 0; h < 2; h++) {
                int rl = wm + mi * 16 + gid + h * 8;
                lsum[rl][warp & 1] = rs[mi][h];
                lsq [rl][warp & 1] = rq[mi][h];
            }
    }
    __syncthreads();
    if (tid < 128) {
        float s = lsum[tid][0] + lsum[tid][1];
        float q = lsq [tid][0] + lsq [tid][1];
        g_lnp[(size_t)(m0 + tid) * 8 + nt] = make_float2(s, q);
    }
}

// -------- finalize LN stats --------
__global__ void ln_fin_kernel() {
    int row = blockIdx.x * 256 + threadIdx.x;
    if (row >= NROWS) return;
    const float2* p = g_lnp + (size_t)row * 8;
    float s = 0.f, q = 0.f;
#pragma unroll
    for (int i = 0; i < 8; i++) { float2 v = p[i]; s += v.x; q += v.y; }
    float mu = s * (1.f / CC);
    float var = q * (1.f / CC) - mu * mu;
    g_stats[row] = make_float2(mu, rsqrtf(var + 1e-5f));
}

// -------- apply LN + transpose back to [B,T,C,HW] --------
__global__ void transpose_out_kernel(const float* __restrict__ ln_g,
                                     const float* __restrict__ ln_b,
                                     float* __restrict__ out) {
    __shared__ float tile[32][33];
    int bt = blockIdx.z;
    int n0 = blockIdx.x * 32;
    int c0 = blockIdx.y * 32;
    int tx = threadIdx.x, ty = threadIdx.y;
    int b = bt >> 6, t = bt & 63;
    float lg = ln_g[c0 + tx], lb = ln_b[c0 + tx];
#pragma unroll
    for (int i = 0; i < 4; i++) {
        int nl = ty + i * 8;
        int n = n0 + nl;
        if (n < HW) {
            int bn = b * HW + n;
            float2 st = g_stats[bn * TT + t];
            float v = g_y[(((size_t)bn) * TT + t) * CC + c0 + tx];
            tile[nl][tx] = (v - st.x) * st.y * lg + lb;
        }
    }
    __syncthreads();
#pragma unroll
    for (int i = 0; i < 4; i++) {
        int cl = ty + i * 8;
        int n = n0 + tx;
        if (n < HW)
            out[((size_t)bt * CC + (c0 + cl)) * HW + n] = tile[tx][cl];
    }
}

extern "C" void kernel_launch(void* const* d_in, const int* in_sizes, int n_in,
                              void* d_out, int out_size) {
    const float* x    = (const float*)d_in[0];
    const float* Wg   = (const float*)d_in[1];
    const float* a1   = (const float*)d_in[2];
    const float* a2   = (const float*)d_in[3];
    const float* W2   = (const float*)d_in[4];
    const float* b2   = (const float*)d_in[5];
    const float* ln_g = (const float*)d_in[6];
    const float* ln_b = (const float*)d_in[7];
    float* out = (float*)d_out;

    cudaFuncSetAttribute(gat_fused_kernel,
                         cudaFuncAttributeMaxDynamicSharedMemorySize, GAT_SMEM);

    transpose_in_kernel<<<dim3(7, 16, BB * TT), dim3(32, 8)>>>(x);
    sel2_kernel<<<BN, 64>>>();
    gat_fused_kernel<<<dim3(NROWS / 128, 8), 256, GAT_SMEM>>>(Wg, a1, a2, out);
    gemm_out_kernel<<<dim3(NROWS / 128, 8), 256>>>(out, W2, b2);
    ln_fin_kernel<<<(NROWS + 255) / 256, 256>>>();
    transpose_out_kernel<<<dim3(7, 16, BB * TT), dim3(32, 8)>>>(ln_g, ln_b, out);
}

// round 16
// speedup vs baseline: 2.9814x; 1.0960x over previous
#include <cuda_runtime.h>
#include <math.h>
#include <stdint.h>

// Problem constants
#define BB 4
#define TT 64
#define CC 512
#define HW 196          // 14*14 spatial positions
#define BN (BB*HW)      // 784
#define NROWS (BN*TT)   // 50176
#define NH 8
#define DH 64
#define KTOP 19         // int(0.3*64)
#define ALPHA 0.2f
// DistanceAdj band: reference's Eigen pexp flushes subnormal outputs ->
// adj0=exp(-(0.6d^2+0.2)) > 0 iff |d| <= 12. (verified)
#define DBAND 12

// -------- device global scratch --------
__device__ float g_xr[(size_t)NROWS * CC];          // [BN,T,C]
__device__ float g_y [(size_t)NROWS * CC];          // pre-LN result
__device__ float2 g_stats[NROWS];                   // (mu, rstd)
__device__ unsigned long long g_sel[BN];            // top-k union mask bits
__device__ float g_magp[(size_t)NROWS * 16];        // per-row sumsq partials
__device__ float2 g_lnp[(size_t)NROWS * 8];         // per-row (sum,sumsq) partials

// -------- helpers --------
__device__ __forceinline__ void mma_tf32(float c[4], const uint32_t a[4], const uint32_t b[2]) {
    asm volatile(
        "mma.sync.aligned.m16n8k8.row.col.f32.tf32.tf32.f32 "
        "{%0,%1,%2,%3}, {%4,%5,%6,%7}, {%8,%9}, {%0,%1,%2,%3};"
        : "+f"(c[0]), "+f"(c[1]), "+f"(c[2]), "+f"(c[3])
        : "r"(a[0]), "r"(a[1]), "r"(a[2]), "r"(a[3]), "r"(b[0]), "r"(b[1]));
}
__device__ __forceinline__ void cp_async16(uint32_t saddr, const void* g) {
    asm volatile("cp.async.cg.shared.global [%0], [%1], 16;" :: "r"(saddr), "l"(g));
}
#define CP_COMMIT() asm volatile("cp.async.commit_group;")
#define CP_WAIT1()  asm volatile("cp.async.wait_group 1;")
#define CP_WAIT0()  asm volatile("cp.async.wait_group 0;")

// -------- kernel 1: transpose x -> xr, emitting sumsq partials --------
__global__ void transpose_in_kernel(const float* __restrict__ x) {
    __shared__ float tile[32][33];
    __shared__ float red[8][33];
    int bt = blockIdx.z;                  // b*64+t
    int n0 = blockIdx.x * 32;
    int c0 = blockIdx.y * 32;
    int tx = threadIdx.x, ty = threadIdx.y;
    int b = bt >> 6, t = bt & 63;
    float part = 0.f;
#pragma unroll
    for (int i = 0; i < 4; i++) {
        int cl = ty + i * 8;
        int n = n0 + tx;
        if (n < HW) {
            float v = x[((size_t)bt * CC + (c0 + cl)) * HW + n];
            tile[cl][tx] = v;
            part = fmaf(v, v, part);
        }
    }
    red[ty][tx] = part;
    __syncthreads();
#pragma unroll
    for (int i = 0; i < 4; i++) {
        int nl = ty + i * 8;
        int n = n0 + nl;
        if (n < HW)
            g_xr[(((size_t)(b * HW + n)) * TT + t) * CC + c0 + tx] = tile[tx][nl];
    }
    if (ty == 0) {
        int n = n0 + tx;
        if (n < HW) {
            float s = 0.f;
#pragma unroll
            for (int r = 0; r < 8; r++) s += red[r][tx];
            g_magp[(((size_t)(b * HW + n)) * TT + t) * 16 + blockIdx.y] = s;
        }
    }
}

// -------- kernel 2: per-bn top-k mask from sumsq partials --------
__global__ void sel2_kernel() {
    __shared__ float m2[64];
    __shared__ unsigned long long mparts[2];
    const int bn = blockIdx.x;
    const int tid = threadIdx.x;   // 0..63
    {
        const float* p = g_magp + ((size_t)bn * TT + tid) * 16;
        float s = 0.f;
#pragma unroll
        for (int i = 0; i < 16; i++) s += p[i];
        m2[tid] = s;               // sumsq; sqrt monotone -> same ranks
    }
    __syncthreads();
    float m = m2[tid];
    int rank = 0;
#pragma unroll 8
    for (int s = 0; s < 64; s++) {
        float ms = m2[s];
        rank += (ms > m) || (ms == m && s < tid);
    }
    unsigned bal = __ballot_sync(~0u, rank < KTOP);
    if ((tid & 31) == 0) mparts[tid >> 5] = bal;
    __syncthreads();
    if (tid == 0) g_sel[bn] = mparts[0] | (mparts[1] << 32);
}

// ===== fused GAT: h-GEMM (tf32 mma, cp.async 2-stage) + attention ====
// grid (392, 8); block 256.
// smem: hh[128][68] | stg{ phase1: As[2][128][36]+Bs[2][32][72] (13824 f)
//                          phase2: att[128][68] (8704 f) }
//       | f1p[128] f2p[128] sa1[64] sa2[64] colp[8][64]
#define STG_FLOATS 13824
#define GAT_SMEM ((128*68 + STG_FLOATS + 128 + 128 + 64 + 64 + 512) * 4)

__global__ __launch_bounds__(256) void gat_fused_kernel(
    const float* __restrict__ Wg, const float* __restrict__ a1g,
    const float* __restrict__ a2g, float* __restrict__ tmp_out) {
    extern __shared__ float smf[];
    float (*hh)[68]  = reinterpret_cast<float(*)[68]>(smf);          // [128][68]
    float* stg = smf + 128 * 68;
    float (*As)[128][36] = reinterpret_cast<float(*)[128][36]>(stg);
    float (*Bs)[32][72]  = reinterpret_cast<float(*)[32][72]>(stg + 2 * 4608);
    float (*att)[68] = reinterpret_cast<float(*)[68]>(stg);          // [128][68]
    float* f1p  = stg + STG_FLOATS;  // [128] logits f1; later inv col norms
    float* f2p  = f1p + 128;         // [128]
    float* sa1  = f2p + 128;         // [64]
    float* sa2  = sa1 + 64;          // [64]
    float* colp = sa2 + 64;          // [8][64]
    __shared__ unsigned long long smask[2];

    const int tid = threadIdx.x;
    const int m0 = blockIdx.x * 128;
    const int head = blockIdx.y;
    const int bn0 = blockIdx.x * 2;
    const int lane = tid & 31, warp = tid >> 5;
    const int gid = lane >> 2, tq = lane & 3;

    if (tid < 64)        sa1[tid]       = a1g[head * DH + tid];
    else if (tid < 128)  sa2[tid - 64]  = a2g[head * DH + (tid - 64)];
    else if (tid == 128) smask[0] = g_sel[bn0];
    else if (tid == 129) smask[1] = g_sel[bn0 + 1];

    // ---- phase 1: h-GEMM, cp.async double-buffered ----
    const float* __restrict__ Bp = Wg + (size_t)head * CC * DH;
    const int wm = (warp >> 1) * 32, wn = (warp & 1) * 32;
    const int sar = tid >> 3, sac = (tid & 7) * 4;
    const int sbr = tid >> 4, sbc = (tid & 15) * 4;
    const uint32_t sA = (uint32_t)__cvta_generic_to_shared(&As[0][0][0]);
    const uint32_t sB = (uint32_t)__cvta_generic_to_shared(&Bs[0][0][0]);

    auto stage = [&](int k0, int s) {
#pragma unroll
        for (int i = 0; i < 4; i++) {
            int r = sar + i * 32;
            cp_async16(sA + ((s * 4608 + r * 36 + sac) << 2),
                       &g_xr[(size_t)(m0 + r) * CC + k0 + sac]);
        }
#pragma unroll
        for (int i = 0; i < 2; i++) {
            int r = sbr + i * 16;
            cp_async16(sB + ((s * 2304 + r * 72 + sbc) << 2),
                       &Bp[(size_t)(k0 + r) * DH + sbc]);
        }
        CP_COMMIT();
    };

    float acc[2][4][4] = {};
    stage(0, 0);
    for (int it = 0; it < 16; it++) {
        if (it + 1 < 16) { stage((it + 1) * 32, (it + 1) & 1); CP_WAIT1(); }
        else CP_WAIT0();
        __syncthreads();
        const int s = it & 1;
#pragma unroll
        for (int ks = 0; ks < 4; ks++) {
            const int k = ks * 8;
            uint32_t af[2][4];
#pragma unroll
            for (int mi = 0; mi < 2; mi++) {
                int base = wm + mi * 16;
                af[mi][0] = __float_as_uint(As[s][base + gid][k + tq]);
                af[mi][1] = __float_as_uint(As[s][base + gid + 8][k + tq]);
                af[mi][2] = __float_as_uint(As[s][base + gid][k + tq + 4]);
                af[mi][3] = __float_as_uint(As[s][base + gid + 8][k + tq + 4]);
            }
            uint32_t bf[4][2];
#pragma unroll
            for (int ni = 0; ni < 4; ni++) {
                int n = wn + ni * 8 + gid;
                bf[ni][0] = __float_as_uint(Bs[s][k + tq][n]);
                bf[ni][1] = __float_as_uint(Bs[s][k + tq + 4][n]);
            }
#pragma unroll
            for (int mi = 0; mi < 2; mi++)
#pragma unroll
                for (int ni = 0; ni < 4; ni++)
                    mma_tf32(acc[mi][ni], af[mi], bf[ni]);
        }
        __syncthreads();
    }
    // store h tile
#pragma unroll
    for (int mi = 0; mi < 2; mi++)
#pragma unroll
        for (int ni = 0; ni < 4; ni++) {
            int r0 = wm + mi * 16 + gid;
            int c0 = wn + ni * 8 + tq * 2;
            float* c = acc[mi][ni];
            hh[r0][c0]         = c[0];
            hh[r0][c0 + 1]     = c[1];
            hh[r0 + 8][c0]     = c[2];
            hh[r0 + 8][c0 + 1] = c[3];
        }
    __syncthreads();

    // ---- phase 2: attention on two 64x64 tiles ----
    {
        int row = tid & 127;
        const float* w = (tid < 128) ? sa1 : sa2;
        float s = 0.f;
#pragma unroll 16
        for (int d = 0; d < 64; d++) s = fmaf(hh[row][d], w[d], s);
        ((tid < 128) ? f1p : f2p)[row] = s;
    }
    __syncthreads();

    const int half = warp >> 2, wl = warp & 3;
    const unsigned long long selm = smask[half];
    for (int t = wl; t < 64; t += 4) {
        unsigned long long band = (t >= DBAND) ? (0x1FFFFFFull << (t - DBAND))
                                               : (0x1FFFFFFull >> (DBAND - t));
        unsigned long long rowm = ((((selm >> t) & 1ull) ? ~0ull : selm)) & band;
        float ft = f1p[half * 64 + t];
        int s0 = lane, s1 = lane + 32;
        float e0 = ft + f2p[half * 64 + s0];
        float e1 = ft + f2p[half * 64 + s1];
        e0 = fmaxf(e0, ALPHA * e0);
        e1 = fmaxf(e1, ALPHA * e1);
        float l0 = ((rowm >> s0) & 1ull) ? e0 : -9e15f;
        float l1 = ((rowm >> s1) & 1ull) ? e1 : -9e15f;
        float mx = fmaxf(l0, l1);
#pragma unroll
        for (int o = 16; o; o >>= 1) mx = fmaxf(mx, __shfl_xor_sync(~0u, mx, o));
        float p0 = __expf(l0 - mx), p1 = __expf(l1 - mx);
        float sumv = p0 + p1;
#pragma unroll
        for (int o = 16; o; o >>= 1) sumv += __shfl_xor_sync(~0u, sumv, o);
        float inv = 1.f / sumv;
        att[half * 64 + t][s0] = p0 * inv;
        att[half * 64 + t][s1] = p1 * inv;
    }
    __syncthreads();

    // D = att @ hh per half
    const int rbase = half * 64;
    float acc2[8][4] = {};
#pragma unroll
    for (int k0 = 0; k0 < 64; k0 += 8) {
        uint32_t af[4];
        af[0] = __float_as_uint(att[rbase + wl * 16 + gid][k0 + tq]);
        af[1] = __float_as_uint(att[rbase + wl * 16 + gid + 8][k0 + tq]);
        af[2] = __float_as_uint(att[rbase + wl * 16 + gid][k0 + tq + 4]);
        af[3] = __float_as_uint(att[rbase + wl * 16 + gid + 8][k0 + tq + 4]);
#pragma unroll
        for (int ni = 0; ni < 8; ni++) {
            int n = ni * 8 + gid;
            uint32_t bf[2];
            bf[0] = __float_as_uint(hh[rbase + k0 + tq][n]);
            bf[1] = __float_as_uint(hh[rbase + k0 + tq + 4][n]);
            mma_tf32(acc2[ni], af, bf);
        }
    }
    __syncthreads();   // all att/hh reads done; reuse hh for sv

    float cpart[16] = {};
#pragma unroll
    for (int ni = 0; ni < 8; ni++) {
        int r0 = rbase + wl * 16 + gid;
        int c0 = ni * 8 + tq * 2;
        float* c = acc2[ni];
#pragma unroll
        for (int q = 0; q < 4; q++) {
            int r = r0 + (q >> 1) * 8, cc = c0 + (q & 1);
            float v = c[q];
            float e = v > 0.f ? v : (__expf(v) - 1.f);
            float ae = fabsf(e);
            hh[r][cc] = copysignf(sqrtf(ae), e);
            cpart[ni * 2 + (q & 1)] += ae;
        }
    }
#pragma unroll
    for (int o = 4; o <= 16; o <<= 1)
#pragma unroll
        for (int j = 0; j < 16; j++)
            cpart[j] += __shfl_xor_sync(~0u, cpart[j], o);
    if (gid == 0) {
#pragma unroll
        for (int ni = 0; ni < 8; ni++) {
            colp[(half * 4 + wl) * 64 + ni * 8 + tq * 2]     = cpart[ni * 2];
            colp[(half * 4 + wl) * 64 + ni * 8 + tq * 2 + 1] = cpart[ni * 2 + 1];
        }
    }
    __syncthreads();
    if (tid < 128) {
        int h = tid >> 6, c = tid & 63;
        float tot = colp[(h * 4 + 0) * 64 + c] + colp[(h * 4 + 1) * 64 + c]
                  + colp[(h * 4 + 2) * 64 + c] + colp[(h * 4 + 3) * 64 + c];
        f1p[tid] = 1.f / fmaxf(sqrtf(tot), 1e-12f);
    }
    __syncthreads();

#pragma unroll
    for (int i = 0; i < 8; i++) {
        int r = (tid >> 4) + i * 16;
        int c4 = (tid & 15) * 4;
        int ib = (r >> 6) * 64;
        float4 o4 = make_float4(hh[r][c4]     * f1p[ib + c4],
                                hh[r][c4 + 1] * f1p[ib + c4 + 1],
                                hh[r][c4 + 2] * f1p[ib + c4 + 2],
                                hh[r][c4 + 3] * f1p[ib + c4 + 3]);
        int bn = bn0 + (r >> 6), t = r & 63;
        *reinterpret_cast<float4*>(
            &tmp_out[((size_t)bn * TT + t) * CC + head * DH + c4]) = o4;
    }
}

// -------- gemm1: g_y = tmp @ W2 + b2 + g_xr, cp.async 2-stage, LN partials ----
__global__ __launch_bounds__(256) void gemm_out_kernel(
    const float* __restrict__ Atmp, const float* __restrict__ Bsrc,
    const float* __restrict__ bias) {
    __shared__ float As[2][128][36];
    __shared__ float Bs[2][32][72];
    __shared__ float lsum[128][2], lsq[128][2];
    const int tid = threadIdx.x;
    const int m0 = blockIdx.x * 128;
    const int nt = blockIdx.y;
    const float* __restrict__ Bp = Bsrc + nt * 64;

    const int lane = tid & 31, warp = tid >> 5;
    const int gid = lane >> 2, tq = lane & 3;
    const int wm = (warp >> 1) * 32, wn = (warp & 1) * 32;
    const int sar = tid >> 3, sac = (tid & 7) * 4;
    const int sbr = tid >> 4, sbc = (tid & 15) * 4;
    const uint32_t sA = (uint32_t)__cvta_generic_to_shared(&As[0][0][0]);
    const uint32_t sB = (uint32_t)__cvta_generic_to_shared(&Bs[0][0][0]);

    auto stage = [&](int k0, int s) {
#pragma unroll
        for (int i = 0; i < 4; i++) {
            int r = sar + i * 32;
            cp_async16(sA + ((s * 4608 + r * 36 + sac) << 2),
                       &Atmp[(size_t)(m0 + r) * CC + k0 + sac]);
        }
#pragma unroll
        for (int i = 0; i < 2; i++) {
            int r = sbr + i * 16;
            cp_async16(sB + ((s * 2304 + r * 72 + sbc) << 2),
                       &Bp[(size_t)(k0 + r) * CC + sbc]);
        }
        CP_COMMIT();
    };

    float acc[2][4][4] = {};
    stage(0, 0);
    for (int it = 0; it < 16; it++) {
        if (it + 1 < 16) { stage((it + 1) * 32, (it + 1) & 1); CP_WAIT1(); }
        else CP_WAIT0();
        __syncthreads();
        const int s = it & 1;
#pragma unroll
        for (int ks = 0; ks < 4; ks++) {
            const int k = ks * 8;
            uint32_t af[2][4];
#pragma unroll
            for (int mi = 0; mi < 2; mi++) {
                int base = wm + mi * 16;
                af[mi][0] = __float_as_uint(As[s][base + gid][k + tq]);
                af[mi][1] = __float_as_uint(As[s][base + gid + 8][k + tq]);
                af[mi][2] = __float_as_uint(As[s][base + gid][k + tq + 4]);
                af[mi][3] = __float_as_uint(As[s][base + gid + 8][k + tq + 4]);
            }
            uint32_t bf[4][2];
#pragma unroll
            for (int ni = 0; ni < 4; ni++) {
                int n = wn + ni * 8 + gid;
                bf[ni][0] = __float_as_uint(Bs[s][k + tq][n]);
                bf[ni][1] = __float_as_uint(Bs[s][k + tq + 4][n]);
            }
#pragma unroll
            for (int mi = 0; mi < 2; mi++)
#pragma unroll
                for (int ni = 0; ni < 4; ni++)
                    mma_tf32(acc[mi][ni], af[mi], bf[ni]);
        }
        __syncthreads();
    }

    const int ncol0 = nt * 64;
    float rs[2][2] = {}, rq[2][2] = {};
#pragma unroll
    for (int mi = 0; mi < 2; mi++)
#pragma unroll
        for (int ni = 0; ni < 4; ni++) {
            int r0 = m0 + wm + mi * 16 + gid;
            int cc = ncol0 + wn + ni * 8 + tq * 2;
            float* c = acc[mi][ni];
            float2 bv = *reinterpret_cast<const float2*>(&bias[cc]);
            float2 x0 = *reinterpret_cast<const float2*>(&g_xr[(size_t)r0 * CC + cc]);
            float2 x1 = *reinterpret_cast<const float2*>(&g_xr[(size_t)(r0 + 8) * CC + cc]);
            float y0x = c[0] + bv.x + x0.x, y0y = c[1] + bv.y + x0.y;
            float y1x = c[2] + bv.x + x1.x, y1y = c[3] + bv.y + x1.y;
            *reinterpret_cast<float2*>(&g_y[(size_t)r0 * CC + cc]) = make_float2(y0x, y0y);
            *reinterpret_cast<float2*>(&g_y[(size_t)(r0 + 8) * CC + cc]) = make_float2(y1x, y1y);
            rs[mi][0] += y0x + y0y; rq[mi][0] = fmaf(y0x, y0x, fmaf(y0y, y0y, rq[mi][0]));
            rs[mi][1] += y1x + y1y; rq[mi][1] = fmaf(y1x, y1x, fmaf(y1y, y1y, rq[mi][1]));
        }
#pragma unroll
    for (int o = 1; o <= 2; o <<= 1)
#pragma unroll
        for (int mi = 0; mi < 2; mi++)
#pragma unroll
            for (int h = 0; h < 2; h++) {
                rs[mi][h] += __shfl_xor_sync(~0u, rs[mi][h], o);
                rq[mi][h] += __shfl_xor_sync(~0u, rq[mi][h], o);
            }
    if (tq == 0) {
#pragma unroll
        for (int mi = 0; mi < 2; mi++)
#pragma unroll
            for (int h = 0; h < 2; h++) {
                int rl = wm + mi * 16 + gid + h * 8;
                lsum[rl][warp & 1] = rs[mi][h];
                lsq [rl][warp & 1] = rq[mi][h];
            }
    }
    __syncthreads();
    if (tid < 128) {
        float s = lsum[tid][0] + lsum[tid][1];
        float q = lsq [tid][0] + lsq [tid][1];
        g_lnp[(size_t)(m0 + tid) * 8 + nt] = make_float2(s, q);
    }
}

// -------- finalize LN stats --------
__global__ void ln_fin_kernel() {
    int row = blockIdx.x * 256 + threadIdx.x;
    if (row >= NROWS) return;
    const float2* p = g_lnp + (size_t)row * 8;
    float s = 0.f, q = 0.f;
#pragma unroll
    for (int i = 0; i < 8; i++) { float2 v = p[i]; s += v.x; q += v.y; }
    float mu = s * (1.f / CC);
    float var = q * (1.f / CC) - mu * mu;
    g_stats[row] = make_float2(mu, rsqrtf(var + 1e-5f));
}

// -------- apply LN + transpose back to [B,T,C,HW] --------
__global__ void transpose_out_kernel(const float* __restrict__ ln_g,
                                     const float* __restrict__ ln_b,
                                     float* __restrict__ out) {
    __shared__ float tile[32][33];
    int bt = blockIdx.z;
    int n0 = blockIdx.x * 32;
    int c0 = blockIdx.y * 32;
    int tx = threadIdx.x, ty = threadIdx.y;
    int b = bt >> 6, t = bt & 63;
    float lg = ln_g[c0 + tx], lb = ln_b[c0 + tx];
#pragma unroll
    for (int i = 0; i < 4; i++) {
        int nl = ty + i * 8;
        int n = n0 + nl;
        if (n < HW) {
            int bn = b * HW + n;
            float2 st = g_stats[bn * TT + t];
            float v = g_y[(((size_t)bn) * TT + t) * CC + c0 + tx];
            tile[nl][tx] = (v - st.x) * st.y * lg + lb;
        }
    }
    __syncthreads();
#pragma unroll
    for (int i = 0; i < 4; i++) {
        int cl = ty + i * 8;
        int n = n0 + tx;
        if (n < HW)
            out[((size_t)bt * CC + (c0 + cl)) * HW + n] = tile[tx][cl];
    }
}

extern "C" void kernel_launch(void* const* d_in, const int* in_sizes, int n_in,
                              void* d_out, int out_size) {
    const float* x    = (const float*)d_in[0];
    const float* Wg   = (const float*)d_in[1];
    const float* a1   = (const float*)d_in[2];
    const float* a2   = (const float*)d_in[3];
    const float* W2   = (const float*)d_in[4];
    const float* b2   = (const float*)d_in[5];
    const float* ln_g = (const float*)d_in[6];
    const float* ln_b = (const float*)d_in[7];
    float* out = (float*)d_out;

    cudaFuncSetAttribute(gat_fused_kernel,
                         cudaFuncAttributeMaxDynamicSharedMemorySize, GAT_SMEM);

    transpose_in_kernel<<<dim3(7, 16, BB * TT), dim3(32, 8)>>>(x);
    sel2_kernel<<<BN, 64>>>();
    gat_fused_kernel<<<dim3(NROWS / 128, 8), 256, GAT_SMEM>>>(Wg, a1, a2, out);
    gemm_out_kernel<<<dim3(NROWS / 128, 8), 256>>>(out, W2, b2);
    ln_fin_kernel<<<(NROWS + 255) / 256, 256>>>();
    transpose_out_kernel<<<dim3(7, 16, BB * TT), dim3(32, 8)>>>(ln_g, ln_b, out);
}